// round 12
// baseline (speedup 1.0000x reference)
#include <cuda_runtime.h>

#define OVERLAP_T 0.5f
#define VAR0 0.1f
#define VAR1 0.2f

#define BMAX 64
#define PMAX 32768
#define OMAX 64
#define NBLK (PMAX/256)
#define BUF1 8192
#define BUF2 1024

// Scratch (static device arrays; zero-initialized at load; each run leaves
// g_key/g_cnt/g_done zeroed again so graph replays see clean state)
__device__ float               g_ce[BMAX * PMAX];
__device__ unsigned long long  g_key[BMAX * OMAX];
__device__ int                 g_npos[BMAX];
__device__ float               g_pl[BMAX * NBLK];
__device__ float               g_pc[BMAX * NBLK];
__device__ int                 g_pn[BMAX * NBLK];
__device__ float               g_fl[BMAX];
__device__ float               g_fc[BMAX];
__device__ float               g_cneg[BMAX];
__device__ unsigned            g_buf1[BMAX * BUF1];
__device__ unsigned            g_buf2[BMAX * BUF2];
__device__ unsigned            g_cnt[BMAX];
__device__ unsigned            g_done;

__device__ __forceinline__ float iou_one(float4 t, float ta,
                                         float px0, float py0, float px1, float py1,
                                         float pa) {
    float lx = fmaxf(t.x, px0), ly = fmaxf(t.y, py0);
    float rx = fminf(t.z, px1), ry = fminf(t.w, py1);
    float w = fmaxf(rx - lx, 0.0f), h = fmaxf(ry - ly, 0.0f);
    float inter = w * h;
    float den = ta + pa - inter;
    return __fdividef(inter, den);
}

__device__ __forceinline__ float sl1_of(float4 l, float4 pr, float4 t) {
    float gcx = ((t.x + t.z) * 0.5f - pr.x) / (VAR0 * pr.z);
    float gcy = ((t.y + t.w) * 0.5f - pr.y) / (VAR0 * pr.w);
    float gw  = __logf((t.z - t.x) / pr.z) * (1.0f / VAR1);
    float gh  = __logf((t.w - t.y) / pr.w) * (1.0f / VAR1);
    float d0 = l.x - gcx, d1 = l.y - gcy, d2 = l.z - gw, d3 = l.w - gh;
    float a0 = fabsf(d0), a1 = fabsf(d1), a2 = fabsf(d2), a3 = fabsf(d3);
    float s0 = (a0 < 1.0f) ? 0.5f * d0 * d0 : a0 - 0.5f;
    float s1 = (a1 < 1.0f) ? 0.5f * d1 * d1 : a1 - 0.5f;
    float s2 = (a2 < 1.0f) ? 0.5f * d2 * d2 : a2 - 0.5f;
    float s3 = (a3 < 1.0f) ? 0.5f * d3 * d3 : a3 - 0.5f;
    return (s0 + s1) + (s2 + s3);
}

__device__ __forceinline__ float lse2(float2 c) {
    float mx = fmaxf(c.x, c.y);
    float mn = fminf(c.x, c.y);
    return mx + __logf(1.0f + __expf(mn - mx));
}

// ---------------------------------------------------------------------------
// Fully fused: match+loss (all blocks) → last block per batch runs
// fixup + radix-select top-k → last batch block runs final reduction.
// ---------------------------------------------------------------------------
__global__ __launch_bounds__(256)
void k_fused(const float* __restrict__ loc,
             const float* __restrict__ conf,
             const float* __restrict__ priors,
             const float* __restrict__ targets,
             float* __restrict__ out,
             int P, int O, int nb, int B) {
    __shared__ float4 tb[OMAX];
    __shared__ float  ta_s[OMAX];
    __shared__ unsigned long long wkey[8 * OMAX];
    __shared__ unsigned hist[2048];
    __shared__ unsigned sfx[2048];
    __shared__ unsigned csum[64], cadd[64];
    __shared__ int      ps[OMAX];
    __shared__ float    wl[8], wc[8], fred[8];
    __shared__ int      wn[8], ired[8];
    __shared__ double   dredA[8], dredC[8];
    __shared__ float    s_dl, s_dc;
    __shared__ int      s_dn, s_np, s_krem, s_chosen, s_last;
    __shared__ unsigned s_above, s_cnt1, s_cnt2, s_arr;

    const int tid  = threadIdx.x;
    const int lane = tid & 31;
    const int wrp  = tid >> 5;
    const int b    = blockIdx.y;
    const int p    = blockIdx.x * 256 + tid;

    // ================= phase 1: match + loss =================
    if (tid < O) {
        const float* t = targets + ((long)b * O + tid) * 5;
        float4 v = make_float4(t[0], t[1], t[2], t[3]);
        tb[tid]   = v;
        ta_s[tid] = (v.z - v.x) * (v.w - v.y);
    }
    __syncthreads();

    float4 pr = reinterpret_cast<const float4*>(priors)[p];
    float px0 = pr.x - pr.z * 0.5f;
    float py0 = pr.y - pr.w * 0.5f;
    float px1 = pr.x + pr.z * 0.5f;
    float py1 = pr.y + pr.w * 0.5f;
    float pa  = (px1 - px0) * (py1 - py0);

    float best = -1.0f;
    int   besto = 0;
    int   pbase = blockIdx.x * 256 + wrp * 32;

    #pragma unroll 4
    for (int o = 0; o < O; o++) {
        float iou = iou_one(tb[o], ta_s[o], px0, py0, px1, py1, pa);
        if (iou > best) { best = iou; besto = o; }

        unsigned ib = __float_as_uint(iou);
        unsigned m  = __reduce_max_sync(0xffffffffu, ib);
        unsigned win = __ballot_sync(0xffffffffu, ib == m);
        if (lane == 0) {
            int src = __ffs(win) - 1;
            wkey[wrp * OMAX + o] =
                ((unsigned long long)m << 32) |
                (unsigned int)(~(unsigned int)(pbase + src));
        }
    }

    long ip = (long)b * P + p;
    int ct = (best >= OVERLAP_T) ? 1 : 0;

    float2 c = reinterpret_cast<const float2*>(conf)[ip];
    float lse = lse2(c);

    float ll = 0.0f, cp = 0.0f, ce_neg;
    int np1 = 0;
    if (ct) {
        np1 = 1;
        cp = lse - c.y;
        ce_neg = 0.0f;
        float4 l = reinterpret_cast<const float4*>(loc)[ip];
        ll = sl1_of(l, pr, tb[besto]);
    } else {
        ce_neg = lse - c.x;
    }
    g_ce[ip] = ce_neg;

    #pragma unroll
    for (int off = 16; off; off >>= 1) {
        ll  += __shfl_xor_sync(0xffffffffu, ll, off);
        cp  += __shfl_xor_sync(0xffffffffu, cp, off);
        np1 += __shfl_xor_sync(0xffffffffu, np1, off);
    }
    if (lane == 0) { wl[wrp] = ll; wc[wrp] = cp; wn[wrp] = np1; }
    __syncthreads();
    if (tid == 0) {
        float a = 0.f, cc = 0.f; int nn = 0;
        #pragma unroll
        for (int w = 0; w < 8; w++) { a += wl[w]; cc += wc[w]; nn += wn[w]; }
        int bi = b * gridDim.x + blockIdx.x;
        g_pl[bi] = a; g_pc[bi] = cc; g_pn[bi] = nn;
    }
    if (tid < O) {
        unsigned long long bk = wkey[tid];
        #pragma unroll
        for (int w = 1; w < 8; w++) {
            unsigned long long k2 = wkey[w * OMAX + tid];
            if (k2 > bk) bk = k2;
        }
        atomicMax(&g_key[b * OMAX + tid], bk);
    }

    // ============ arrival: last block of batch b continues ============
    __threadfence();
    __syncthreads();
    if (tid == 0) s_arr = atomicAdd(&g_cnt[b], 1u);
    __syncthreads();
    if (s_arr != (unsigned)(gridDim.x - 1)) return;
    __threadfence();   // acquire: other blocks' g_ce/g_pn/g_key now visible

    // ================= phase 2: fixup + top-k (256 threads) =================
    if (tid == 0) {
        g_cnt[b] = 0u;   // reset for next graph replay
        s_dl = 0.f; s_dc = 0.f; s_dn = 0; s_cnt1 = 0u; s_cnt2 = 0u;
    }
    for (int i = tid; i < 2048; i += 256) hist[i] = 0u;

    int np = 0;
    for (int j = tid; j < nb; j += 256) np += g_pn[b * nb + j];
    #pragma unroll
    for (int off = 16; off; off >>= 1) np += __shfl_xor_sync(0xffffffffu, np, off);
    if (lane == 0) ired[wrp] = np;
    if (tid < O) {
        ps[tid] = (int)(~(unsigned int)(g_key[b * OMAX + tid] & 0xffffffffull));
        g_key[b * OMAX + tid] = 0ull;   // reset for next graph replay
    }
    __syncthreads();
    if (tid == 0) {
        int acc0 = 0;
        #pragma unroll
        for (int w = 0; w < 8; w++) acc0 += ired[w];
        s_np = acc0;
    }

    if (tid < O) {
        int pp = ps[tid];
        bool dup = false;
        for (int o2 = tid + 1; o2 < O; o2++) if (ps[o2] == pp) dup = true;
        if (!dup) {
            float4 pr2 = reinterpret_cast<const float4*>(priors)[pp];
            float qx0 = pr2.x - pr2.z * 0.5f;
            float qy0 = pr2.y - pr2.w * 0.5f;
            float qx1 = pr2.x + pr2.z * 0.5f;
            float qy1 = pr2.y + pr2.w * 0.5f;
            float qa  = (qx1 - qx0) * (qy1 - qy0);

            float bst = -1.0f; int bo = 0;
            for (int oo = 0; oo < O; oo++) {
                const float* tt = targets + ((long)b * O + oo) * 5;
                float4 t = make_float4(tt[0], tt[1], tt[2], tt[3]);
                float ta = (t.z - t.x) * (t.w - t.y);
                float iou = iou_one(t, ta, qx0, qy0, qx1, qy1, qa);
                if (iou > bst) { bst = iou; bo = oo; }
            }
            int ct2 = (bst >= OVERLAP_T) ? 1 : 0;

            long ip2 = (long)b * P + pp;
            float4 l = reinterpret_cast<const float4*>(loc)[ip2];
            const float* tf = targets + ((long)b * O + tid) * 5;
            float4 tnew = make_float4(tf[0], tf[1], tf[2], tf[3]);
            float sl_new = sl1_of(l, pr2, tnew);

            if (ct2) {
                const float* to = targets + ((long)b * O + bo) * 5;
                float4 told = make_float4(to[0], to[1], to[2], to[3]);
                atomicAdd(&s_dl, sl_new - sl1_of(l, pr2, told));
            } else {
                float2 c2 = reinterpret_cast<const float2*>(conf)[ip2];
                float lse2v = lse2(c2);
                atomicAdd(&s_dl, sl_new);
                atomicAdd(&s_dc, lse2v - c2.y);
                atomicAdd(&s_dn, 1);
                g_ce[ip2] = 0.0f;   // ordered before pass A by __syncthreads
            }
        }
    }
    __syncthreads();

    int npos = s_np + s_dn;
    int k = 3 * npos; if (k > P - 1) k = P - 1;
    if (tid == 0) {
        g_npos[b] = npos;
        g_fl[b] = s_dl;
        g_fc[b] = s_dc;
        s_krem = k;
    }
    __syncthreads();

    float acc = 0.0f;
    int c1 = 0, c2v = 0, c3 = 0;

    if (k > 0) {
        const float* v = g_ce + (long)b * P;
        const uint4* v4 = reinterpret_cast<const uint4*>(v);
        int P4 = P >> 2;
        unsigned* buf1 = g_buf1 + b * BUF1;
        unsigned* buf2 = g_buf2 + b * BUF2;

        // ---- pass A: round-1 histogram, 2×uint4 per iteration (MLP 8) ----
        for (int i = tid; i < P4; i += 512) {
            uint4 ua = v4[i];
            int i2 = i + 256;
            uint4 ub = (i2 < P4) ? v4[i2] : make_uint4(0xffffffffu, 0xffffffffu,
                                                        0xffffffffu, 0xffffffffu);
            atomicAdd(&hist[ua.x >> 21], 1u);
            atomicAdd(&hist[ua.y >> 21], 1u);
            atomicAdd(&hist[ua.z >> 21], 1u);
            atomicAdd(&hist[ua.w >> 21], 1u);
            if (i2 < P4) {
                atomicAdd(&hist[ub.x >> 21], 1u);
                atomicAdd(&hist[ub.y >> 21], 1u);
                atomicAdd(&hist[ub.z >> 21], 1u);
                atomicAdd(&hist[ub.w >> 21], 1u);
            }
        }
        __syncthreads();

        #define SELECT_BIN(NBINS)                                               \
        {                                                                       \
            for (int i = tid; i < (NBINS); i += 256) {                          \
                unsigned val = hist[i];                                         \
                _Pragma("unroll")                                               \
                for (int off = 1; off < 32; off <<= 1) {                        \
                    unsigned t2 = __shfl_down_sync(0xffffffffu, val, off);      \
                    if (lane + off < 32) val += t2;                             \
                }                                                               \
                sfx[i] = val;                                                   \
                if (lane == 0) csum[i >> 5] = val;                              \
            }                                                                   \
            __syncthreads();                                                    \
            int nch = (NBINS) >> 5;                                             \
            if (tid < nch) {                                                    \
                unsigned add = 0;                                               \
                for (int j = tid + 1; j < nch; j++) add += csum[j];             \
                cadd[tid] = add;                                                \
            }                                                                   \
            __syncthreads();                                                    \
            for (int i = tid; i < (NBINS); i += 256) sfx[i] += cadd[i >> 5];    \
            __syncthreads();                                                    \
            int krem = s_krem;                                                  \
            for (int i = tid; i < (NBINS); i += 256) {                          \
                unsigned s  = sfx[i];                                           \
                unsigned sn = (i + 1 < (NBINS)) ? sfx[i + 1] : 0u;              \
                if ((int)s >= krem && (int)sn < krem) {                         \
                    s_chosen = i; s_above = sn;                                 \
                }                                                               \
            }                                                                   \
            __syncthreads();                                                    \
            if (tid == 0) s_krem -= (int)s_above;                               \
        }

        SELECT_BIN(2048);
        c1 = s_chosen;
        for (int i = tid; i < 2048; i += 256) hist[i] = 0u;
        __syncthreads();

        // ---- pass B: bins>c1 → acc; ==c1 → compact (gmem buf) + hist2 ----
        for (int i = tid; i < P4; i += 256) {
            uint4 u = v4[i];
            #pragma unroll
            for (int e = 0; e < 4; e++) {
                unsigned ue = (e == 0) ? u.x : (e == 1) ? u.y : (e == 2) ? u.z : u.w;
                int bin = (int)(ue >> 21);
                if (bin > c1) acc += __uint_as_float(ue);
                else if (bin == c1) {
                    unsigned pos = atomicAdd(&s_cnt1, 1u);
                    if (pos < BUF1) buf1[pos] = ue;
                    atomicAdd(&hist[(ue >> 10) & 0x7FFu], 1u);
                }
            }
        }
        __syncthreads();

        SELECT_BIN(2048);
        c2v = s_chosen;
        unsigned S1 = s_cnt1;
        for (int i = tid; i < 1024; i += 256) hist[i] = 0u;
        __syncthreads();

        // ---- pass C: survivors bins2>c2 → acc, ==c2 → compact ----
        if (S1 <= BUF1) {
            for (unsigned i = tid; i < S1; i += 256) {
                unsigned u = buf1[i];
                int bin2 = (int)((u >> 10) & 0x7FFu);
                if (bin2 > c2v) acc += __uint_as_float(u);
                else if (bin2 == c2v) {
                    unsigned pos = atomicAdd(&s_cnt2, 1u);
                    if (pos < BUF2) buf2[pos] = u;
                    atomicAdd(&hist[u & 0x3FFu], 1u);
                }
            }
        } else {
            for (int i = tid; i < P; i += 256) {
                unsigned u = __float_as_uint(v[i]);
                if ((int)(u >> 21) != c1) continue;
                int bin2 = (int)((u >> 10) & 0x7FFu);
                if (bin2 > c2v) acc += __uint_as_float(u);
                else if (bin2 == c2v) {
                    unsigned pos = atomicAdd(&s_cnt2, 1u);
                    if (pos < BUF2) buf2[pos] = u;
                    atomicAdd(&hist[u & 0x3FFu], 1u);
                }
            }
        }
        __syncthreads();

        SELECT_BIN(1024);
        c3 = s_chosen;
        unsigned S2 = s_cnt2;
        __syncthreads();

        // ---- pass D: final strictly-greater among exact-tie bin ----
        if (S2 <= BUF2) {
            for (unsigned i = tid; i < S2; i += 256) {
                unsigned u = buf2[i];
                if ((int)(u & 0x3FFu) > c3) acc += __uint_as_float(u);
            }
        } else {
            for (int i = tid; i < P; i += 256) {
                unsigned u = __float_as_uint(v[i]);
                if ((int)(u >> 21) == c1 && (int)((u >> 10) & 0x7FFu) == c2v &&
                    (int)(u & 0x3FFu) > c3)
                    acc += __uint_as_float(u);
            }
        }

        #pragma unroll
        for (int off = 16; off; off >>= 1)
            acc += __shfl_xor_sync(0xffffffffu, acc, off);
        if (lane == 0) fred[wrp] = acc;
        __syncthreads();
        if (tid == 0) {
            float tot = 0.f;
            #pragma unroll
            for (int w = 0; w < 8; w++) tot += fred[w];
            unsigned tbits = ((unsigned)c1 << 21) | ((unsigned)c2v << 10) | (unsigned)c3;
            g_cneg[b] = tot + (float)s_krem * __uint_as_float(tbits);
        }
    } else {
        if (tid == 0) g_cneg[b] = 0.0f;
    }

    // ================= phase 3: last batch does final reduction =============
    __threadfence();
    __syncthreads();
    if (tid == 0) {
        unsigned old = atomicAdd(&g_done, 1u);
        s_last = (old == (unsigned)(B - 1));
    }
    __syncthreads();
    if (!s_last) return;
    __threadfence();

    double a = 0.0, cc = 0.0;
    int n = 0;
    int tot = B * nb;
    for (int i = tid; i < tot; i += 256) { a += (double)g_pl[i]; cc += (double)g_pc[i]; }
    for (int i = tid; i < B; i += 256) {
        a  += (double)g_fl[i];
        cc += (double)g_fc[i] + (double)g_cneg[i];
        n  += g_npos[i];
    }
    #pragma unroll
    for (int off = 16; off; off >>= 1) {
        a  += __shfl_xor_sync(0xffffffffu, a, off);
        cc += __shfl_xor_sync(0xffffffffu, cc, off);
        n  += __shfl_xor_sync(0xffffffffu, n, off);
    }
    if (lane == 0) { dredA[wrp] = a; dredC[wrp] = cc; ired[wrp] = n; }
    __syncthreads();
    if (tid == 0) {
        double ta = 0.0, tc = 0.0; int tn = 0;
        #pragma unroll
        for (int w = 0; w < 8; w++) { ta += dredA[w]; tc += dredC[w]; tn += ired[w]; }
        double N = (double)tn;
        if (N < 1.0) N = 1.0;
        out[0] = (float)(ta / N);
        out[1] = (float)(tc / N);
        g_done = 0u;                    // reset for next graph replay
    }
}

extern "C" void kernel_launch(void* const* d_in, const int* in_sizes, int n_in,
                              void* d_out, int out_size) {
    const float* loc     = (const float*)d_in[0];
    const float* conf    = (const float*)d_in[1];
    const float* priors  = (const float*)d_in[2];
    const float* targets = (const float*)d_in[3];
    float* out = (float*)d_out;

    int P = in_sizes[2] / 4;
    int B = in_sizes[0] / (P * 4);
    int O = in_sizes[3] / (B * 5);
    int nb = (P + 255) / 256;

    dim3 grid(nb, B);
    k_fused<<<grid, 256>>>(loc, conf, priors, targets, out, P, O, nb, B);
}

// round 13
// speedup vs baseline: 1.4349x; 1.4349x over previous
#include <cuda_runtime.h>

#define OVERLAP_T 0.5f
#define VAR0 0.1f
#define VAR1 0.2f

#define BMAX 64
#define PMAX 32768
#define OMAX 64
#define NBLK (PMAX/256)
#define BUF1 8192
#define BUF2 1024
// dynamic smem layout (uints): sd[PMAX] | buf1[BUF1] | buf2[BUF2] | hist[2048] | sfx[2048]
#define DSMEM_WORDS (PMAX + BUF1 + BUF2 + 2048 + 2048)

// Scratch (static device arrays; zero-initialized at load; each run leaves
// g_key/g_done zeroed again so graph replays see clean state)
__device__ float               g_ce[BMAX * PMAX];
__device__ unsigned long long  g_key[BMAX * OMAX];
__device__ int                 g_npos[BMAX];
__device__ float               g_pl[BMAX * NBLK];
__device__ float               g_pc[BMAX * NBLK];
__device__ int                 g_pn[BMAX * NBLK];
__device__ float               g_fl[BMAX];
__device__ float               g_fc[BMAX];
__device__ float               g_cneg[BMAX];
__device__ unsigned            g_done;

__device__ __forceinline__ float iou_one(float4 t, float ta,
                                         float px0, float py0, float px1, float py1,
                                         float pa) {
    float lx = fmaxf(t.x, px0), ly = fmaxf(t.y, py0);
    float rx = fminf(t.z, px1), ry = fminf(t.w, py1);
    float w = fmaxf(rx - lx, 0.0f), h = fmaxf(ry - ly, 0.0f);
    float inter = w * h;
    float den = ta + pa - inter;
    return __fdividef(inter, den);
}

__device__ __forceinline__ float sl1_of(float4 l, float4 pr, float4 t) {
    float gcx = ((t.x + t.z) * 0.5f - pr.x) / (VAR0 * pr.z);
    float gcy = ((t.y + t.w) * 0.5f - pr.y) / (VAR0 * pr.w);
    float gw  = __logf((t.z - t.x) / pr.z) * (1.0f / VAR1);
    float gh  = __logf((t.w - t.y) / pr.w) * (1.0f / VAR1);
    float d0 = l.x - gcx, d1 = l.y - gcy, d2 = l.z - gw, d3 = l.w - gh;
    float a0 = fabsf(d0), a1 = fabsf(d1), a2 = fabsf(d2), a3 = fabsf(d3);
    float s0 = (a0 < 1.0f) ? 0.5f * d0 * d0 : a0 - 0.5f;
    float s1 = (a1 < 1.0f) ? 0.5f * d1 * d1 : a1 - 0.5f;
    float s2 = (a2 < 1.0f) ? 0.5f * d2 * d2 : a2 - 0.5f;
    float s3 = (a3 < 1.0f) ? 0.5f * d3 * d3 : a3 - 0.5f;
    return (s0 + s1) + (s2 + s3);
}

__device__ __forceinline__ float lse2(float2 c) {
    float mx = fmaxf(c.x, c.y);
    float mn = fminf(c.x, c.y);
    return mx + __logf(1.0f + __expf(mn - mx));
}

// ---------------------------------------------------------------------------
// Fused match + loss. Per-truth warp argmax via REDUX.SYNC; per-warp smem
// slots; block epilogue does one global atomicMax per truth.
// Templated on O so the match loop fully unrolls for the common O=16.
// ---------------------------------------------------------------------------
template<int OC>
__device__ __forceinline__ void k_main_body(
    const float* __restrict__ loc, const float* __restrict__ conf,
    const float* __restrict__ priors, const float* __restrict__ targets,
    int P, int O) {
    int b    = blockIdx.y;
    int tid  = threadIdx.x;
    int lane = tid & 31;
    int wrp  = tid >> 5;
    int p    = blockIdx.x * blockDim.x + tid;

    __shared__ float4 tb[OMAX];
    __shared__ float  ta_s[OMAX];
    __shared__ unsigned long long wkey[8 * OMAX];   // [warp][o]

    const int On = (OC > 0) ? OC : O;

    if (tid < On) {
        const float* t = targets + ((long)b * On + tid) * 5;
        float4 v = make_float4(t[0], t[1], t[2], t[3]);
        tb[tid]   = v;
        ta_s[tid] = (v.z - v.x) * (v.w - v.y);
    }
    __syncthreads();

    float4 pr = reinterpret_cast<const float4*>(priors)[p];
    float px0 = pr.x - pr.z * 0.5f;
    float py0 = pr.y - pr.w * 0.5f;
    float px1 = pr.x + pr.z * 0.5f;
    float py1 = pr.y + pr.w * 0.5f;
    float pa  = (px1 - px0) * (py1 - py0);

    float best = -1.0f;
    int   besto = 0;
    int   pbase = blockIdx.x * blockDim.x + wrp * 32;

    #pragma unroll
    for (int o = 0; o < On; o++) {
        float iou = iou_one(tb[o], ta_s[o], px0, py0, px1, py1, pa);
        if (iou > best) { best = iou; besto = o; }

        // warp max + first-occurrence argmax (IoU >= 0 → u32 order == float order)
        unsigned ib = __float_as_uint(iou);
        unsigned m  = __reduce_max_sync(0xffffffffu, ib);
        unsigned win = __ballot_sync(0xffffffffu, ib == m);
        if (lane == 0) {
            int src = __ffs(win) - 1;
            wkey[wrp * OMAX + o] =
                ((unsigned long long)m << 32) |
                (unsigned int)(~(unsigned int)(pbase + src));
        }
    }

    long ip = (long)b * P + p;
    int ct = (best >= OVERLAP_T) ? 1 : 0;

    float2 c = reinterpret_cast<const float2*>(conf)[ip];
    float lse = lse2(c);

    float ll = 0.0f, cp = 0.0f, ce_neg;
    int np = 0;
    if (ct) {
        np = 1;
        cp = lse - c.y;
        ce_neg = 0.0f;
        float4 l = reinterpret_cast<const float4*>(loc)[ip];
        ll = sl1_of(l, pr, tb[besto]);
    } else {
        ce_neg = lse - c.x;
    }
    g_ce[ip] = ce_neg;

    #pragma unroll
    for (int off = 16; off; off >>= 1) {
        ll += __shfl_xor_sync(0xffffffffu, ll, off);
        cp += __shfl_xor_sync(0xffffffffu, cp, off);
        np += __shfl_xor_sync(0xffffffffu, np, off);
    }
    __shared__ float wl[8], wc[8];
    __shared__ int   wn[8];
    if (lane == 0) { wl[wrp] = ll; wc[wrp] = cp; wn[wrp] = np; }
    __syncthreads();
    if (tid == 0) {
        float a = 0.f, cc = 0.f; int nn = 0;
        #pragma unroll
        for (int w = 0; w < 8; w++) { a += wl[w]; cc += wc[w]; nn += wn[w]; }
        int bi = b * gridDim.x + blockIdx.x;
        g_pl[bi] = a; g_pc[bi] = cc; g_pn[bi] = nn;
    }
    if (tid < On) {
        unsigned long long bk = wkey[tid];
        #pragma unroll
        for (int w = 1; w < 8; w++) {
            unsigned long long k2 = wkey[w * OMAX + tid];
            if (k2 > bk) bk = k2;
        }
        atomicMax(&g_key[b * OMAX + tid], bk);
    }
}

__global__ __launch_bounds__(256)
void k_main(const float* __restrict__ loc,
            const float* __restrict__ conf,
            const float* __restrict__ priors,
            const float* __restrict__ targets,
            int P, int O) {
    if (O == 16) k_main_body<16>(loc, conf, priors, targets, P, O);
    else         k_main_body<0>(loc, conf, priors, targets, P, O);
}

// ---------------------------------------------------------------------------
// Fused fixup + radix-select top-k + (last block) final reduction.
// Passes A/B vectorized (uint4); plain per-element smem atomics.
// ---------------------------------------------------------------------------
__global__ __launch_bounds__(1024)
void k_topk(const float* __restrict__ loc,
            const float* __restrict__ conf,
            const float* __restrict__ priors,
            const float* __restrict__ targets,
            float* __restrict__ out,
            int P, int O, int nb, int B) {
    extern __shared__ unsigned dyn[];
    unsigned* sd   = dyn;                 // P staged values
    unsigned* buf1 = dyn + P;             // BUF1
    unsigned* buf2 = buf1 + BUF1;         // BUF2
    unsigned* hist = buf2 + BUF2;         // 2048
    unsigned* sfx  = hist + 2048;         // 2048

    __shared__ unsigned csum[64], cadd[64];
    __shared__ int      ps[OMAX];
    __shared__ float    fred[32];
    __shared__ int      ired[32];
    __shared__ double   dredA[32], dredC[32];
    __shared__ float    s_dl, s_dc;
    __shared__ int      s_dn, s_np, s_krem, s_chosen, s_last;
    __shared__ unsigned s_above, s_cnt1, s_cnt2;

    int b    = blockIdx.x;
    int tid  = threadIdx.x;
    int lane = tid & 31;
    int wrp  = tid >> 5;

    // ---------------- fixup prologue ----------------
    if (tid == 0) { s_dl = 0.f; s_dc = 0.f; s_dn = 0; s_cnt1 = 0u; s_cnt2 = 0u; }
    int np = 0;
    for (int j = tid; j < nb; j += 1024) np += g_pn[b * nb + j];
    #pragma unroll
    for (int off = 16; off; off >>= 1) np += __shfl_xor_sync(0xffffffffu, np, off);
    if (lane == 0) ired[wrp] = np;
    if (tid < O) {
        ps[tid] = (int)(~(unsigned int)(g_key[b * OMAX + tid] & 0xffffffffull));
        g_key[b * OMAX + tid] = 0ull;   // reset for next graph replay
    }
    __syncthreads();
    if (tid == 0) {
        int acc0 = 0;
        #pragma unroll
        for (int w = 0; w < 32; w++) acc0 += ired[w];
        s_np = acc0;
    }

    if (tid < O) {
        int p = ps[tid];
        bool dup = false;
        for (int o2 = tid + 1; o2 < O; o2++) if (ps[o2] == p) dup = true;
        if (!dup) {
            float4 pr = reinterpret_cast<const float4*>(priors)[p];
            float px0 = pr.x - pr.z * 0.5f;
            float py0 = pr.y - pr.w * 0.5f;
            float px1 = pr.x + pr.z * 0.5f;
            float py1 = pr.y + pr.w * 0.5f;
            float pa  = (px1 - px0) * (py1 - py0);

            float best = -1.0f; int bo = 0;
            for (int oo = 0; oo < O; oo++) {
                const float* tt = targets + ((long)b * O + oo) * 5;
                float4 t = make_float4(tt[0], tt[1], tt[2], tt[3]);
                float ta = (t.z - t.x) * (t.w - t.y);
                float iou = iou_one(t, ta, px0, py0, px1, py1, pa);
                if (iou > best) { best = iou; bo = oo; }
            }
            int ct = (best >= OVERLAP_T) ? 1 : 0;

            long ip = (long)b * P + p;
            float4 l = reinterpret_cast<const float4*>(loc)[ip];
            const float* tf = targets + ((long)b * O + tid) * 5;
            float4 tnew = make_float4(tf[0], tf[1], tf[2], tf[3]);
            float sl_new = sl1_of(l, pr, tnew);

            if (ct) {
                const float* to = targets + ((long)b * O + bo) * 5;
                float4 told = make_float4(to[0], to[1], to[2], to[3]);
                atomicAdd(&s_dl, sl_new - sl1_of(l, pr, told));
            } else {
                float2 c = reinterpret_cast<const float2*>(conf)[ip];
                float lse = lse2(c);
                atomicAdd(&s_dl, sl_new);
                atomicAdd(&s_dc, lse - c.y);
                atomicAdd(&s_dn, 1);
                g_ce[ip] = 0.0f;   // ordered before the load pass by __syncthreads
            }
        }
    }
    for (int i = tid; i < 2048; i += 1024) hist[i] = 0u;
    __syncthreads();

    int npos = s_np + s_dn;
    int k = 3 * npos; if (k > P - 1) k = P - 1;
    if (tid == 0) {
        g_npos[b] = npos;
        g_fl[b] = s_dl;
        g_fc[b] = s_dc;
        s_krem = k;
    }
    __syncthreads();

    float acc = 0.0f;
    int c1 = 0, c2 = 0, c3 = 0;

    if (k > 0) {
        const uint4* v4 = reinterpret_cast<const uint4*>(g_ce + (long)b * P);
        uint4* sd4 = reinterpret_cast<uint4*>(sd);
        int P4 = P >> 2;

        // ---- pass A (vectorized): load uint4 + round-1 histogram ----
        for (int i = tid; i < P4; i += 1024) {
            uint4 u = v4[i];
            sd4[i] = u;
            atomicAdd(&hist[u.x >> 21], 1u);
            atomicAdd(&hist[u.y >> 21], 1u);
            atomicAdd(&hist[u.z >> 21], 1u);
            atomicAdd(&hist[u.w >> 21], 1u);
        }
        __syncthreads();

        // ---- selection helper: parallel suffix scan + crossing find ----
        #define SELECT_BIN(NBINS)                                               \
        {                                                                       \
            for (int i = tid; i < (NBINS); i += 1024) {                         \
                unsigned val = hist[i];                                         \
                _Pragma("unroll")                                               \
                for (int off = 1; off < 32; off <<= 1) {                        \
                    unsigned t2 = __shfl_down_sync(0xffffffffu, val, off);      \
                    if (lane + off < 32) val += t2;                             \
                }                                                               \
                sfx[i] = val;                                                   \
                if (lane == 0) csum[i >> 5] = val;                              \
            }                                                                   \
            __syncthreads();                                                    \
            int nch = (NBINS) >> 5;                                             \
            if (tid < nch) {                                                    \
                unsigned add = 0;                                               \
                for (int j = tid + 1; j < nch; j++) add += csum[j];             \
                cadd[tid] = add;                                                \
            }                                                                   \
            __syncthreads();                                                    \
            for (int i = tid; i < (NBINS); i += 1024) sfx[i] += cadd[i >> 5];   \
            __syncthreads();                                                    \
            int krem = s_krem;                                                  \
            for (int i = tid; i < (NBINS); i += 1024) {                         \
                unsigned s  = sfx[i];                                           \
                unsigned sn = (i + 1 < (NBINS)) ? sfx[i + 1] : 0u;              \
                if ((int)s >= krem && (int)sn < krem) {                         \
                    s_chosen = i; s_above = sn;                                 \
                }                                                               \
            }                                                                   \
            __syncthreads();                                                    \
            if (tid == 0) s_krem -= (int)s_above;                               \
        }

        SELECT_BIN(2048);
        c1 = s_chosen;
        for (int i = tid; i < 2048; i += 1024) hist[i] = 0u;
        __syncthreads();

        // ---- pass B (vectorized): bins>c1 → acc; ==c1 → compact + hist2 ----
        for (int i = tid; i < P4; i += 1024) {
            uint4 u = sd4[i];
            #pragma unroll
            for (int e = 0; e < 4; e++) {
                unsigned ue = (e == 0) ? u.x : (e == 1) ? u.y : (e == 2) ? u.z : u.w;
                int bin = (int)(ue >> 21);
                if (bin > c1) acc += __uint_as_float(ue);
                else if (bin == c1) {
                    unsigned pos = atomicAdd(&s_cnt1, 1u);
                    if (pos < BUF1) buf1[pos] = ue;
                    atomicAdd(&hist[(ue >> 10) & 0x7FFu], 1u);
                }
            }
        }
        __syncthreads();

        SELECT_BIN(2048);
        c2 = s_chosen;
        unsigned S1 = s_cnt1;
        if (tid < 1024) hist[tid] = 0u;
        __syncthreads();

        // ---- pass C: among survivors, bins2>c2 → acc, ==c2 → compact ----
        if (S1 <= BUF1) {
            for (unsigned i = tid; i < S1; i += 1024) {
                unsigned u = buf1[i];
                int bin2 = (int)((u >> 10) & 0x7FFu);
                if (bin2 > c2) acc += __uint_as_float(u);
                else if (bin2 == c2) {
                    unsigned pos = atomicAdd(&s_cnt2, 1u);
                    if (pos < BUF2) buf2[pos] = u;
                    atomicAdd(&hist[u & 0x3FFu], 1u);
                }
            }
        } else {
            for (int i = tid; i < P; i += 1024) {
                unsigned u = sd[i];
                if ((int)(u >> 21) != c1) continue;
                int bin2 = (int)((u >> 10) & 0x7FFu);
                if (bin2 > c2) acc += __uint_as_float(u);
                else if (bin2 == c2) {
                    unsigned pos = atomicAdd(&s_cnt2, 1u);
                    if (pos < BUF2) buf2[pos] = u;
                    atomicAdd(&hist[u & 0x3FFu], 1u);
                }
            }
        }
        __syncthreads();

        SELECT_BIN(1024);
        c3 = s_chosen;
        unsigned S2 = s_cnt2;
        __syncthreads();

        // ---- pass D: final strictly-greater among exact-tie bin ----
        if (S2 <= BUF2) {
            for (unsigned i = tid; i < S2; i += 1024) {
                unsigned u = buf2[i];
                if ((int)(u & 0x3FFu) > c3) acc += __uint_as_float(u);
            }
        } else {
            for (int i = tid; i < P; i += 1024) {
                unsigned u = sd[i];
                if ((int)(u >> 21) == c1 && (int)((u >> 10) & 0x7FFu) == c2 &&
                    (int)(u & 0x3FFu) > c3)
                    acc += __uint_as_float(u);
            }
        }

        // block reduce acc
        #pragma unroll
        for (int off = 16; off; off >>= 1)
            acc += __shfl_xor_sync(0xffffffffu, acc, off);
        if (lane == 0) fred[wrp] = acc;
        __syncthreads();
        if (tid == 0) {
            float tot = 0.f;
            #pragma unroll
            for (int w = 0; w < 32; w++) tot += fred[w];
            unsigned tbits = ((unsigned)c1 << 21) | ((unsigned)c2 << 10) | (unsigned)c3;
            g_cneg[b] = tot + (float)s_krem * __uint_as_float(tbits);
        }
    } else {
        if (tid == 0) g_cneg[b] = 0.0f;
    }

    // ---------------- last-block final reduction ----------------
    if (tid == 0) {
        __threadfence();
        unsigned old = atomicAdd(&g_done, 1u);
        s_last = (old == (unsigned)(B - 1));
    }
    __syncthreads();
    if (!s_last) return;
    __threadfence();

    double a = 0.0, cc = 0.0;
    int n = 0;
    int tot = B * nb;
    for (int i = tid; i < tot; i += 1024) { a += (double)g_pl[i]; cc += (double)g_pc[i]; }
    for (int i = tid; i < B; i += 1024) {
        a  += (double)g_fl[i];
        cc += (double)g_fc[i] + (double)g_cneg[i];
        n  += g_npos[i];
    }
    #pragma unroll
    for (int off = 16; off; off >>= 1) {
        a  += __shfl_xor_sync(0xffffffffu, a, off);
        cc += __shfl_xor_sync(0xffffffffu, cc, off);
        n  += __shfl_xor_sync(0xffffffffu, n, off);
    }
    if (lane == 0) { dredA[wrp] = a; dredC[wrp] = cc; ired[wrp] = n; }
    __syncthreads();
    if (tid == 0) {
        double ta = 0.0, tc = 0.0; int tn = 0;
        #pragma unroll
        for (int w = 0; w < 32; w++) { ta += dredA[w]; tc += dredC[w]; tn += ired[w]; }
        double N = (double)tn;
        if (N < 1.0) N = 1.0;
        out[0] = (float)(ta / N);
        out[1] = (float)(tc / N);
        g_done = 0u;                    // reset for next graph replay
    }
}

extern "C" void kernel_launch(void* const* d_in, const int* in_sizes, int n_in,
                              void* d_out, int out_size) {
    const float* loc     = (const float*)d_in[0];
    const float* conf    = (const float*)d_in[1];
    const float* priors  = (const float*)d_in[2];
    const float* targets = (const float*)d_in[3];
    float* out = (float*)d_out;

    int P = in_sizes[2] / 4;
    int B = in_sizes[0] / (P * 4);
    int O = in_sizes[3] / (B * 5);
    int nb = (P + 255) / 256;

    static int smem_set = 0;
    if (!smem_set) {
        cudaFuncSetAttribute(k_topk, cudaFuncAttributeMaxDynamicSharedMemorySize,
                             DSMEM_WORDS * 4);
        smem_set = 1;
    }

    dim3 grid(nb, B);
    k_main<<<grid, 256>>>(loc, conf, priors, targets, P, O);
    k_topk<<<B, 1024, DSMEM_WORDS * 4>>>(
        loc, conf, priors, targets, out, P, O, nb, B);
}

// round 14
// speedup vs baseline: 1.6458x; 1.1470x over previous
#include <cuda_runtime.h>

#define OVERLAP_T 0.5f
#define VAR0 0.1f
#define VAR1 0.2f

#define BMAX 64
#define PMAX 32768
#define OMAX 64
#define NBLK (PMAX/256)
#define BUF1 8192
#define BUF2 1024
// dynamic smem layout (uints): sd[PMAX] | buf1[BUF1] | buf2[BUF2] | hist[2048] | sfx[2048]
#define DSMEM_WORDS (PMAX + BUF1 + BUF2 + 2048 + 2048)

// Scratch (static device arrays; zero-initialized at load; each run leaves
// g_key/g_done zeroed again so graph replays see clean state)
__device__ float               g_ce[BMAX * PMAX];
__device__ unsigned long long  g_key[BMAX * OMAX];
__device__ int                 g_npos[BMAX];
__device__ float               g_pl[BMAX * NBLK];
__device__ float               g_pc[BMAX * NBLK];
__device__ int                 g_pn[BMAX * NBLK];
__device__ float               g_fl[BMAX];
__device__ float               g_fc[BMAX];
__device__ float               g_cneg[BMAX];
__device__ unsigned            g_done;

__device__ __forceinline__ float iou_one(float4 t, float ta,
                                         float px0, float py0, float px1, float py1,
                                         float pa) {
    float lx = fmaxf(t.x, px0), ly = fmaxf(t.y, py0);
    float rx = fminf(t.z, px1), ry = fminf(t.w, py1);
    float w = fmaxf(rx - lx, 0.0f), h = fmaxf(ry - ly, 0.0f);
    float inter = w * h;
    float den = ta + pa - inter;
    return __fdividef(inter, den);
}

__device__ __forceinline__ float sl1_of(float4 l, float4 pr, float4 t) {
    float gcx = ((t.x + t.z) * 0.5f - pr.x) / (VAR0 * pr.z);
    float gcy = ((t.y + t.w) * 0.5f - pr.y) / (VAR0 * pr.w);
    float gw  = __logf((t.z - t.x) / pr.z) * (1.0f / VAR1);
    float gh  = __logf((t.w - t.y) / pr.w) * (1.0f / VAR1);
    float d0 = l.x - gcx, d1 = l.y - gcy, d2 = l.z - gw, d3 = l.w - gh;
    float a0 = fabsf(d0), a1 = fabsf(d1), a2 = fabsf(d2), a3 = fabsf(d3);
    float s0 = (a0 < 1.0f) ? 0.5f * d0 * d0 : a0 - 0.5f;
    float s1 = (a1 < 1.0f) ? 0.5f * d1 * d1 : a1 - 0.5f;
    float s2 = (a2 < 1.0f) ? 0.5f * d2 * d2 : a2 - 0.5f;
    float s3 = (a3 < 1.0f) ? 0.5f * d3 * d3 : a3 - 0.5f;
    return (s0 + s1) + (s2 + s3);
}

__device__ __forceinline__ float lse2(float2 c) {
    float mx = fmaxf(c.x, c.y);
    float mn = fminf(c.x, c.y);
    return mx + __logf(1.0f + __expf(mn - mx));
}

// ---------------------------------------------------------------------------
// Paired match + loss: each thread handles priors 2t and 2t+1 (adjacent →
// first-occurrence tie-break preserved: lowest tie lane has the lowest index,
// and within a lane p0 < p1). Halves warp-collective ops, smem loads, and
// loop overhead; conf loads become float4, ce stores float2.
// ---------------------------------------------------------------------------
__global__ __launch_bounds__(256)
void k_main2(const float* __restrict__ loc,
             const float* __restrict__ conf,
             const float* __restrict__ priors,
             const float* __restrict__ targets,
             int P) {
    const int O = 16;
    int b    = blockIdx.y;
    int tid  = threadIdx.x;
    int lane = tid & 31;
    int wrp  = tid >> 5;
    int t2   = blockIdx.x * blockDim.x + tid;   // pair index
    int p0   = 2 * t2;
    int p1   = p0 + 1;

    __shared__ float4 tb[O];
    __shared__ float  ta_s[O];
    __shared__ unsigned long long wkey[8 * O];   // [warp][o]

    if (tid < O) {
        const float* t = targets + ((long)b * O + tid) * 5;
        float4 v = make_float4(t[0], t[1], t[2], t[3]);
        tb[tid]   = v;
        ta_s[tid] = (v.z - v.x) * (v.w - v.y);
    }
    __syncthreads();

    float4 prA = reinterpret_cast<const float4*>(priors)[p0];
    float4 prB = reinterpret_cast<const float4*>(priors)[p1];
    float ax0 = prA.x - prA.z * 0.5f, ay0 = prA.y - prA.w * 0.5f;
    float ax1 = prA.x + prA.z * 0.5f, ay1 = prA.y + prA.w * 0.5f;
    float aa  = (ax1 - ax0) * (ay1 - ay0);
    float bx0 = prB.x - prB.z * 0.5f, by0 = prB.y - prB.w * 0.5f;
    float bx1 = prB.x + prB.z * 0.5f, by1 = prB.y + prB.w * 0.5f;
    float ba  = (bx1 - bx0) * (by1 - by0);

    float bestA = -1.0f, bestB = -1.0f;
    int   boA = 0, boB = 0;

    #pragma unroll 4
    for (int o = 0; o < O; o++) {
        float4 t = tb[o];
        float ta = ta_s[o];
        float iouA = iou_one(t, ta, ax0, ay0, ax1, ay1, aa);
        float iouB = iou_one(t, ta, bx0, by0, bx1, by1, ba);
        if (iouA > bestA) { bestA = iouA; boA = o; }
        if (iouB > bestB) { bestB = iouB; boB = o; }

        unsigned ibA = __float_as_uint(iouA);
        unsigned ibB = __float_as_uint(iouB);
        unsigned ibt = (ibB > ibA) ? ibB : ibA;     // tie → prefer p0
        unsigned m   = __reduce_max_sync(0xffffffffu, ibt);
        unsigned win = __ballot_sync(0xffffffffu, ibt == m);
        if (lane == (int)(__ffs(win) - 1)) {
            int psel = (ibB > ibA) ? p1 : p0;
            wkey[wrp * O + o] =
                ((unsigned long long)m << 32) |
                (unsigned int)(~(unsigned int)psel);
        }
    }

    long ipb = (long)b * P;
    // conf pair: floats [2*p0 .. 2*p0+3] = one float4 at index (ipb+p0)/2
    float4 c4 = reinterpret_cast<const float4*>(conf)[(ipb >> 1) + t2];
    float lseA = lse2(make_float2(c4.x, c4.y));
    float lseB = lse2(make_float2(c4.z, c4.w));

    int ctA = (bestA >= OVERLAP_T) ? 1 : 0;
    int ctB = (bestB >= OVERLAP_T) ? 1 : 0;

    float ll = 0.0f, cp = 0.0f;
    float ceA, ceB;
    int np = ctA + ctB;
    if (ctA) {
        cp += lseA - c4.y;
        ceA = 0.0f;
        float4 l = reinterpret_cast<const float4*>(loc)[ipb + p0];
        ll += sl1_of(l, prA, tb[boA]);
    } else {
        ceA = lseA - c4.x;
    }
    if (ctB) {
        cp += lseB - c4.w;
        ceB = 0.0f;
        float4 l = reinterpret_cast<const float4*>(loc)[ipb + p1];
        ll += sl1_of(l, prB, tb[boB]);
    } else {
        ceB = lseB - c4.z;
    }
    reinterpret_cast<float2*>(g_ce)[(ipb >> 1) + t2] = make_float2(ceA, ceB);

    #pragma unroll
    for (int off = 16; off; off >>= 1) {
        ll += __shfl_xor_sync(0xffffffffu, ll, off);
        cp += __shfl_xor_sync(0xffffffffu, cp, off);
        np += __shfl_xor_sync(0xffffffffu, np, off);
    }
    __shared__ float wl[8], wc[8];
    __shared__ int   wn[8];
    if (lane == 0) { wl[wrp] = ll; wc[wrp] = cp; wn[wrp] = np; }
    __syncthreads();
    if (tid == 0) {
        float a = 0.f, cc = 0.f; int nn = 0;
        #pragma unroll
        for (int w = 0; w < 8; w++) { a += wl[w]; cc += wc[w]; nn += wn[w]; }
        int bi = b * gridDim.x + blockIdx.x;
        g_pl[bi] = a; g_pc[bi] = cc; g_pn[bi] = nn;
    }
    if (tid < O) {
        unsigned long long bk = wkey[tid];
        #pragma unroll
        for (int w = 1; w < 8; w++) {
            unsigned long long k2 = wkey[w * O + tid];
            if (k2 > bk) bk = k2;
        }
        atomicMax(&g_key[b * OMAX + tid], bk);
    }
}

// ---------------------------------------------------------------------------
// Generic fallback (one prior/thread) for O != 16 or P % 512 != 0.
// ---------------------------------------------------------------------------
__global__ __launch_bounds__(256)
void k_main1(const float* __restrict__ loc,
             const float* __restrict__ conf,
             const float* __restrict__ priors,
             const float* __restrict__ targets,
             int P, int O) {
    int b    = blockIdx.y;
    int tid  = threadIdx.x;
    int lane = tid & 31;
    int wrp  = tid >> 5;
    int p    = blockIdx.x * blockDim.x + tid;

    __shared__ float4 tb[OMAX];
    __shared__ float  ta_s[OMAX];
    __shared__ unsigned long long wkey[8 * OMAX];

    if (tid < O) {
        const float* t = targets + ((long)b * O + tid) * 5;
        float4 v = make_float4(t[0], t[1], t[2], t[3]);
        tb[tid]   = v;
        ta_s[tid] = (v.z - v.x) * (v.w - v.y);
    }
    __syncthreads();

    bool valid = (p < P);
    float4 pr = valid ? reinterpret_cast<const float4*>(priors)[p]
                      : make_float4(0.f, 0.f, 1.f, 1.f);
    float px0 = pr.x - pr.z * 0.5f;
    float py0 = pr.y - pr.w * 0.5f;
    float px1 = pr.x + pr.z * 0.5f;
    float py1 = pr.y + pr.w * 0.5f;
    float pa  = (px1 - px0) * (py1 - py0);

    float best = -1.0f;
    int   besto = 0;

    #pragma unroll 4
    for (int o = 0; o < O; o++) {
        float iou = valid ? iou_one(tb[o], ta_s[o], px0, py0, px1, py1, pa) : 0.0f;
        if (iou > best) { best = iou; besto = o; }

        unsigned ib = valid ? __float_as_uint(iou) : 0u;
        unsigned m  = __reduce_max_sync(0xffffffffu, ib);
        unsigned win = __ballot_sync(0xffffffffu, ib == m);
        if (lane == (int)(__ffs(win) - 1)) {
            wkey[wrp * OMAX + o] =
                ((unsigned long long)m << 32) |
                (unsigned int)(~(unsigned int)p);
        }
    }

    float ll = 0.0f, cp = 0.0f;
    int np = 0;
    if (valid) {
        long ip = (long)b * P + p;
        int ct = (best >= OVERLAP_T) ? 1 : 0;
        float2 c = reinterpret_cast<const float2*>(conf)[ip];
        float lse = lse2(c);
        float ce_neg;
        if (ct) {
            np = 1;
            cp = lse - c.y;
            ce_neg = 0.0f;
            float4 l = reinterpret_cast<const float4*>(loc)[ip];
            ll = sl1_of(l, pr, tb[besto]);
        } else {
            ce_neg = lse - c.x;
        }
        g_ce[ip] = ce_neg;
    }

    #pragma unroll
    for (int off = 16; off; off >>= 1) {
        ll += __shfl_xor_sync(0xffffffffu, ll, off);
        cp += __shfl_xor_sync(0xffffffffu, cp, off);
        np += __shfl_xor_sync(0xffffffffu, np, off);
    }
    __shared__ float wl[8], wc[8];
    __shared__ int   wn[8];
    if (lane == 0) { wl[wrp] = ll; wc[wrp] = cp; wn[wrp] = np; }
    __syncthreads();
    if (tid == 0) {
        float a = 0.f, cc = 0.f; int nn = 0;
        #pragma unroll
        for (int w = 0; w < 8; w++) { a += wl[w]; cc += wc[w]; nn += wn[w]; }
        int bi = b * gridDim.x + blockIdx.x;
        g_pl[bi] = a; g_pc[bi] = cc; g_pn[bi] = nn;
    }
    if (tid < O) {
        unsigned long long bk = wkey[tid];
        #pragma unroll
        for (int w = 1; w < 8; w++) {
            unsigned long long k2 = wkey[w * OMAX + tid];
            if (k2 > bk) bk = k2;
        }
        atomicMax(&g_key[b * OMAX + tid], bk);
    }
}

// ---------------------------------------------------------------------------
// Fused fixup + radix-select top-k + (last block) final reduction.
// (byte-identical to the measured 77.8µs R8 version)
// ---------------------------------------------------------------------------
__global__ __launch_bounds__(1024)
void k_topk(const float* __restrict__ loc,
            const float* __restrict__ conf,
            const float* __restrict__ priors,
            const float* __restrict__ targets,
            float* __restrict__ out,
            int P, int O, int nb, int B) {
    extern __shared__ unsigned dyn[];
    unsigned* sd   = dyn;
    unsigned* buf1 = dyn + P;
    unsigned* buf2 = buf1 + BUF1;
    unsigned* hist = buf2 + BUF2;
    unsigned* sfx  = hist + 2048;

    __shared__ unsigned csum[64], cadd[64];
    __shared__ int      ps[OMAX];
    __shared__ float    fred[32];
    __shared__ int      ired[32];
    __shared__ double   dredA[32], dredC[32];
    __shared__ float    s_dl, s_dc;
    __shared__ int      s_dn, s_np, s_krem, s_chosen, s_last;
    __shared__ unsigned s_above, s_cnt1, s_cnt2;

    int b    = blockIdx.x;
    int tid  = threadIdx.x;
    int lane = tid & 31;
    int wrp  = tid >> 5;

    if (tid == 0) { s_dl = 0.f; s_dc = 0.f; s_dn = 0; s_cnt1 = 0u; s_cnt2 = 0u; }
    int np = 0;
    for (int j = tid; j < nb; j += 1024) np += g_pn[b * nb + j];
    #pragma unroll
    for (int off = 16; off; off >>= 1) np += __shfl_xor_sync(0xffffffffu, np, off);
    if (lane == 0) ired[wrp] = np;
    if (tid < O) {
        ps[tid] = (int)(~(unsigned int)(g_key[b * OMAX + tid] & 0xffffffffull));
        g_key[b * OMAX + tid] = 0ull;
    }
    __syncthreads();
    if (tid == 0) {
        int acc0 = 0;
        #pragma unroll
        for (int w = 0; w < 32; w++) acc0 += ired[w];
        s_np = acc0;
    }

    if (tid < O) {
        int p = ps[tid];
        bool dup = false;
        for (int o2 = tid + 1; o2 < O; o2++) if (ps[o2] == p) dup = true;
        if (!dup) {
            float4 pr = reinterpret_cast<const float4*>(priors)[p];
            float px0 = pr.x - pr.z * 0.5f;
            float py0 = pr.y - pr.w * 0.5f;
            float px1 = pr.x + pr.z * 0.5f;
            float py1 = pr.y + pr.w * 0.5f;
            float pa  = (px1 - px0) * (py1 - py0);

            float best = -1.0f; int bo = 0;
            for (int oo = 0; oo < O; oo++) {
                const float* tt = targets + ((long)b * O + oo) * 5;
                float4 t = make_float4(tt[0], tt[1], tt[2], tt[3]);
                float ta = (t.z - t.x) * (t.w - t.y);
                float iou = iou_one(t, ta, px0, py0, px1, py1, pa);
                if (iou > best) { best = iou; bo = oo; }
            }
            int ct = (best >= OVERLAP_T) ? 1 : 0;

            long ip = (long)b * P + p;
            float4 l = reinterpret_cast<const float4*>(loc)[ip];
            const float* tf = targets + ((long)b * O + tid) * 5;
            float4 tnew = make_float4(tf[0], tf[1], tf[2], tf[3]);
            float sl_new = sl1_of(l, pr, tnew);

            if (ct) {
                const float* to = targets + ((long)b * O + bo) * 5;
                float4 told = make_float4(to[0], to[1], to[2], to[3]);
                atomicAdd(&s_dl, sl_new - sl1_of(l, pr, told));
            } else {
                float2 c = reinterpret_cast<const float2*>(conf)[ip];
                float lse = lse2(c);
                atomicAdd(&s_dl, sl_new);
                atomicAdd(&s_dc, lse - c.y);
                atomicAdd(&s_dn, 1);
                g_ce[ip] = 0.0f;
            }
        }
    }
    for (int i = tid; i < 2048; i += 1024) hist[i] = 0u;
    __syncthreads();

    int npos = s_np + s_dn;
    int k = 3 * npos; if (k > P - 1) k = P - 1;
    if (tid == 0) {
        g_npos[b] = npos;
        g_fl[b] = s_dl;
        g_fc[b] = s_dc;
        s_krem = k;
    }
    __syncthreads();

    float acc = 0.0f;
    int c1 = 0, c2 = 0, c3 = 0;

    if (k > 0) {
        const uint4* v4 = reinterpret_cast<const uint4*>(g_ce + (long)b * P);
        uint4* sd4 = reinterpret_cast<uint4*>(sd);
        int P4 = P >> 2;

        for (int i = tid; i < P4; i += 1024) {
            uint4 u = v4[i];
            sd4[i] = u;
            atomicAdd(&hist[u.x >> 21], 1u);
            atomicAdd(&hist[u.y >> 21], 1u);
            atomicAdd(&hist[u.z >> 21], 1u);
            atomicAdd(&hist[u.w >> 21], 1u);
        }
        __syncthreads();

        #define SELECT_BIN(NBINS)                                               \
        {                                                                       \
            for (int i = tid; i < (NBINS); i += 1024) {                         \
                unsigned val = hist[i];                                         \
                _Pragma("unroll")                                               \
                for (int off = 1; off < 32; off <<= 1) {                        \
                    unsigned t2 = __shfl_down_sync(0xffffffffu, val, off);      \
                    if (lane + off < 32) val += t2;                             \
                }                                                               \
                sfx[i] = val;                                                   \
                if (lane == 0) csum[i >> 5] = val;                              \
            }                                                                   \
            __syncthreads();                                                    \
            int nch = (NBINS) >> 5;                                             \
            if (tid < nch) {                                                    \
                unsigned add = 0;                                               \
                for (int j = tid + 1; j < nch; j++) add += csum[j];             \
                cadd[tid] = add;                                                \
            }                                                                   \
            __syncthreads();                                                    \
            for (int i = tid; i < (NBINS); i += 1024) sfx[i] += cadd[i >> 5];   \
            __syncthreads();                                                    \
            int krem = s_krem;                                                  \
            for (int i = tid; i < (NBINS); i += 1024) {                         \
                unsigned s  = sfx[i];                                           \
                unsigned sn = (i + 1 < (NBINS)) ? sfx[i + 1] : 0u;              \
                if ((int)s >= krem && (int)sn < krem) {                         \
                    s_chosen = i; s_above = sn;                                 \
                }                                                               \
            }                                                                   \
            __syncthreads();                                                    \
            if (tid == 0) s_krem -= (int)s_above;                               \
        }

        SELECT_BIN(2048);
        c1 = s_chosen;
        for (int i = tid; i < 2048; i += 1024) hist[i] = 0u;
        __syncthreads();

        for (int i = tid; i < P4; i += 1024) {
            uint4 u = sd4[i];
            #pragma unroll
            for (int e = 0; e < 4; e++) {
                unsigned ue = (e == 0) ? u.x : (e == 1) ? u.y : (e == 2) ? u.z : u.w;
                int bin = (int)(ue >> 21);
                if (bin > c1) acc += __uint_as_float(ue);
                else if (bin == c1) {
                    unsigned pos = atomicAdd(&s_cnt1, 1u);
                    if (pos < BUF1) buf1[pos] = ue;
                    atomicAdd(&hist[(ue >> 10) & 0x7FFu], 1u);
                }
            }
        }
        __syncthreads();

        SELECT_BIN(2048);
        c2 = s_chosen;
        unsigned S1 = s_cnt1;
        if (tid < 1024) hist[tid] = 0u;
        __syncthreads();

        if (S1 <= BUF1) {
            for (unsigned i = tid; i < S1; i += 1024) {
                unsigned u = buf1[i];
                int bin2 = (int)((u >> 10) & 0x7FFu);
                if (bin2 > c2) acc += __uint_as_float(u);
                else if (bin2 == c2) {
                    unsigned pos = atomicAdd(&s_cnt2, 1u);
                    if (pos < BUF2) buf2[pos] = u;
                    atomicAdd(&hist[u & 0x3FFu], 1u);
                }
            }
        } else {
            for (int i = tid; i < P; i += 1024) {
                unsigned u = sd[i];
                if ((int)(u >> 21) != c1) continue;
                int bin2 = (int)((u >> 10) & 0x7FFu);
                if (bin2 > c2) acc += __uint_as_float(u);
                else if (bin2 == c2) {
                    unsigned pos = atomicAdd(&s_cnt2, 1u);
                    if (pos < BUF2) buf2[pos] = u;
                    atomicAdd(&hist[u & 0x3FFu], 1u);
                }
            }
        }
        __syncthreads();

        SELECT_BIN(1024);
        c3 = s_chosen;
        unsigned S2 = s_cnt2;
        __syncthreads();

        if (S2 <= BUF2) {
            for (unsigned i = tid; i < S2; i += 1024) {
                unsigned u = buf2[i];
                if ((int)(u & 0x3FFu) > c3) acc += __uint_as_float(u);
            }
        } else {
            for (int i = tid; i < P; i += 1024) {
                unsigned u = sd[i];
                if ((int)(u >> 21) == c1 && (int)((u >> 10) & 0x7FFu) == c2 &&
                    (int)(u & 0x3FFu) > c3)
                    acc += __uint_as_float(u);
            }
        }

        #pragma unroll
        for (int off = 16; off; off >>= 1)
            acc += __shfl_xor_sync(0xffffffffu, acc, off);
        if (lane == 0) fred[wrp] = acc;
        __syncthreads();
        if (tid == 0) {
            float tot = 0.f;
            #pragma unroll
            for (int w = 0; w < 32; w++) tot += fred[w];
            unsigned tbits = ((unsigned)c1 << 21) | ((unsigned)c2 << 10) | (unsigned)c3;
            g_cneg[b] = tot + (float)s_krem * __uint_as_float(tbits);
        }
    } else {
        if (tid == 0) g_cneg[b] = 0.0f;
    }

    if (tid == 0) {
        __threadfence();
        unsigned old = atomicAdd(&g_done, 1u);
        s_last = (old == (unsigned)(B - 1));
    }
    __syncthreads();
    if (!s_last) return;
    __threadfence();

    double a = 0.0, cc = 0.0;
    int n = 0;
    int tot = B * nb;
    for (int i = tid; i < tot; i += 1024) { a += (double)g_pl[i]; cc += (double)g_pc[i]; }
    for (int i = tid; i < B; i += 1024) {
        a  += (double)g_fl[i];
        cc += (double)g_fc[i] + (double)g_cneg[i];
        n  += g_npos[i];
    }
    #pragma unroll
    for (int off = 16; off; off >>= 1) {
        a  += __shfl_xor_sync(0xffffffffu, a, off);
        cc += __shfl_xor_sync(0xffffffffu, cc, off);
        n  += __shfl_xor_sync(0xffffffffu, n, off);
    }
    if (lane == 0) { dredA[wrp] = a; dredC[wrp] = cc; ired[wrp] = n; }
    __syncthreads();
    if (tid == 0) {
        double ta = 0.0, tc = 0.0; int tn = 0;
        #pragma unroll
        for (int w = 0; w < 32; w++) { ta += dredA[w]; tc += dredC[w]; tn += ired[w]; }
        double N = (double)tn;
        if (N < 1.0) N = 1.0;
        out[0] = (float)(ta / N);
        out[1] = (float)(tc / N);
        g_done = 0u;
    }
}

extern "C" void kernel_launch(void* const* d_in, const int* in_sizes, int n_in,
                              void* d_out, int out_size) {
    const float* loc     = (const float*)d_in[0];
    const float* conf    = (const float*)d_in[1];
    const float* priors  = (const float*)d_in[2];
    const float* targets = (const float*)d_in[3];
    float* out = (float*)d_out;

    int P = in_sizes[2] / 4;
    int B = in_sizes[0] / (P * 4);
    int O = in_sizes[3] / (B * 5);

    static int smem_set = 0;
    if (!smem_set) {
        cudaFuncSetAttribute(k_topk, cudaFuncAttributeMaxDynamicSharedMemorySize,
                             DSMEM_WORDS * 4);
        smem_set = 1;
    }

    int nb;
    if (O == 16 && (P % 512) == 0) {
        nb = P / 512;
        dim3 grid(nb, B);
        k_main2<<<grid, 256>>>(loc, conf, priors, targets, P);
    } else {
        nb = (P + 255) / 256;
        dim3 grid(nb, B);
        k_main1<<<grid, 256>>>(loc, conf, priors, targets, P, O);
    }
    k_topk<<<B, 1024, DSMEM_WORDS * 4>>>(
        loc, conf, priors, targets, out, P, O, nb, B);
}

// round 16
// speedup vs baseline: 1.6957x; 1.0303x over previous
#include <cuda_runtime.h>

#define OVERLAP_T 0.5f
#define VAR0 0.1f
#define VAR1 0.2f

#define BMAX 64
#define PMAX 32768
#define OMAX 64
#define NBLK (PMAX/256)
#define BUF1 8192
#define BUF2 1024
// dynamic smem layout (uints): sd[PMAX] | buf1[BUF1] | buf2[BUF2] | hist[2048] | sfx[2048]
#define DSMEM_WORDS (PMAX + BUF1 + BUF2 + 2048 + 2048)

// Scratch (static device arrays; zero-initialized at load; each run leaves
// g_key/g_done zeroed again so graph replays see clean state)
__device__ float               g_ce[BMAX * PMAX];
__device__ unsigned long long  g_key[BMAX * OMAX];
__device__ int                 g_npos[BMAX];
__device__ float               g_pl[BMAX * NBLK];
__device__ float               g_pc[BMAX * NBLK];
__device__ int                 g_pn[BMAX * NBLK];
__device__ float               g_fl[BMAX];
__device__ float               g_fc[BMAX];
__device__ float               g_cneg[BMAX];
__device__ unsigned            g_done;

__device__ __forceinline__ float iou_one(float4 t, float ta,
                                         float px0, float py0, float px1, float py1,
                                         float pa) {
    float lx = fmaxf(t.x, px0), ly = fmaxf(t.y, py0);
    float rx = fminf(t.z, px1), ry = fminf(t.w, py1);
    float w = fmaxf(rx - lx, 0.0f), h = fmaxf(ry - ly, 0.0f);
    float inter = w * h;
    float den = ta + pa - inter;
    return __fdividef(inter, den);
}

__device__ __forceinline__ float sl1_of(float4 l, float4 pr, float4 t) {
    float gcx = ((t.x + t.z) * 0.5f - pr.x) / (VAR0 * pr.z);
    float gcy = ((t.y + t.w) * 0.5f - pr.y) / (VAR0 * pr.w);
    float gw  = __logf((t.z - t.x) / pr.z) * (1.0f / VAR1);
    float gh  = __logf((t.w - t.y) / pr.w) * (1.0f / VAR1);
    float d0 = l.x - gcx, d1 = l.y - gcy, d2 = l.z - gw, d3 = l.w - gh;
    float a0 = fabsf(d0), a1 = fabsf(d1), a2 = fabsf(d2), a3 = fabsf(d3);
    float s0 = (a0 < 1.0f) ? 0.5f * d0 * d0 : a0 - 0.5f;
    float s1 = (a1 < 1.0f) ? 0.5f * d1 * d1 : a1 - 0.5f;
    float s2 = (a2 < 1.0f) ? 0.5f * d2 * d2 : a2 - 0.5f;
    float s3 = (a3 < 1.0f) ? 0.5f * d3 * d3 : a3 - 0.5f;
    return (s0 + s1) + (s2 + s3);
}

__device__ __forceinline__ float lse2(float2 c) {
    float mx = fmaxf(c.x, c.y);
    float mn = fminf(c.x, c.y);
    return mx + __logf(1.0f + __expf(mn - mx));
}

// ---------------------------------------------------------------------------
// Quad match + loss: each thread handles priors 4t..4t+3 (adjacent blocking →
// first-occurrence tie-break preserved: strictly-greater chain prefers the
// lowest index within a lane; lowest tied lane has the lowest index group).
// ---------------------------------------------------------------------------
__global__ __launch_bounds__(256)
void k_main4(const float* __restrict__ loc,
             const float* __restrict__ conf,
             const float* __restrict__ priors,
             const float* __restrict__ targets,
             int P) {
    const int O = 16;
    int b    = blockIdx.y;
    int tid  = threadIdx.x;
    int lane = tid & 31;
    int wrp  = tid >> 5;
    int t4   = blockIdx.x * blockDim.x + tid;   // quad index
    int p0   = 4 * t4;

    __shared__ float4 tb[O];
    __shared__ float  ta_s[O];
    __shared__ unsigned long long wkey[8 * O];   // [warp][o]

    if (tid < O) {
        const float* t = targets + ((long)b * O + tid) * 5;
        float4 v = make_float4(t[0], t[1], t[2], t[3]);
        tb[tid]   = v;
        ta_s[tid] = (v.z - v.x) * (v.w - v.y);
    }
    __syncthreads();

    float x0[4], y0[4], x1[4], y1[4], ar[4];
    float4 prq[4];
    #pragma unroll
    for (int q = 0; q < 4; q++) {
        prq[q] = reinterpret_cast<const float4*>(priors)[p0 + q];
        x0[q] = prq[q].x - prq[q].z * 0.5f;
        y0[q] = prq[q].y - prq[q].w * 0.5f;
        x1[q] = prq[q].x + prq[q].z * 0.5f;
        y1[q] = prq[q].y + prq[q].w * 0.5f;
        ar[q] = (x1[q] - x0[q]) * (y1[q] - y0[q]);
    }

    float bestq[4] = {-1.f, -1.f, -1.f, -1.f};
    int   boq[4]   = {0, 0, 0, 0};

    #pragma unroll 4
    for (int o = 0; o < O; o++) {
        float4 t = tb[o];
        float ta = ta_s[o];
        float iou[4];
        #pragma unroll
        for (int q = 0; q < 4; q++) {
            iou[q] = iou_one(t, ta, x0[q], y0[q], x1[q], y1[q], ar[q]);
            if (iou[q] > bestq[q]) { bestq[q] = iou[q]; boq[q] = o; }
        }
        // lane-local argmax over 4, strictly-greater → lowest index on ties
        unsigned cur = __float_as_uint(iou[0]);
        int sel = 0;
        #pragma unroll
        for (int q = 1; q < 4; q++) {
            unsigned ibq = __float_as_uint(iou[q]);
            if (ibq > cur) { cur = ibq; sel = q; }
        }
        unsigned m   = __reduce_max_sync(0xffffffffu, cur);
        unsigned win = __ballot_sync(0xffffffffu, cur == m);
        if (lane == (int)(__ffs(win) - 1)) {
            wkey[wrp * O + o] =
                ((unsigned long long)m << 32) |
                (unsigned int)(~(unsigned int)(p0 + sel));
        }
    }

    long ipb = (long)b * P;
    // conf for 4 priors = 8 floats = 2 float4 at base (b*P)/2 + 2*t4
    const float4* c4p = reinterpret_cast<const float4*>(conf) + (ipb >> 1) + 2 * t4;
    float4 c01 = c4p[0];
    float4 c23 = c4p[1];
    float2 cq[4] = { make_float2(c01.x, c01.y), make_float2(c01.z, c01.w),
                     make_float2(c23.x, c23.y), make_float2(c23.z, c23.w) };

    float ll = 0.0f, cp = 0.0f;
    float ce[4];
    int np = 0;
    #pragma unroll
    for (int q = 0; q < 4; q++) {
        float lse = lse2(cq[q]);
        if (bestq[q] >= OVERLAP_T) {
            np += 1;
            cp += lse - cq[q].y;
            ce[q] = 0.0f;
            float4 l = reinterpret_cast<const float4*>(loc)[ipb + p0 + q];
            ll += sl1_of(l, prq[q], tb[boq[q]]);
        } else {
            ce[q] = lse - cq[q].x;
        }
    }
    reinterpret_cast<float4*>(g_ce)[(ipb >> 2) + t4] =
        make_float4(ce[0], ce[1], ce[2], ce[3]);

    #pragma unroll
    for (int off = 16; off; off >>= 1) {
        ll += __shfl_xor_sync(0xffffffffu, ll, off);
        cp += __shfl_xor_sync(0xffffffffu, cp, off);
        np += __shfl_xor_sync(0xffffffffu, np, off);
    }
    __shared__ float wl[8], wc[8];
    __shared__ int   wn[8];
    if (lane == 0) { wl[wrp] = ll; wc[wrp] = cp; wn[wrp] = np; }
    __syncthreads();
    if (tid == 0) {
        float a = 0.f, cc = 0.f; int nn = 0;
        #pragma unroll
        for (int w = 0; w < 8; w++) { a += wl[w]; cc += wc[w]; nn += wn[w]; }
        int bi = b * gridDim.x + blockIdx.x;
        g_pl[bi] = a; g_pc[bi] = cc; g_pn[bi] = nn;
    }
    if (tid < O) {
        unsigned long long bk = wkey[tid];
        #pragma unroll
        for (int w = 1; w < 8; w++) {
            unsigned long long k2 = wkey[w * O + tid];
            if (k2 > bk) bk = k2;
        }
        atomicMax(&g_key[b * OMAX + tid], bk);
    }
}

// ---------------------------------------------------------------------------
// Generic fallback (one prior/thread) for O != 16 or P % 1024 != 0.
// ---------------------------------------------------------------------------
__global__ __launch_bounds__(256)
void k_main1(const float* __restrict__ loc,
             const float* __restrict__ conf,
             const float* __restrict__ priors,
             const float* __restrict__ targets,
             int P, int O) {
    int b    = blockIdx.y;
    int tid  = threadIdx.x;
    int lane = tid & 31;
    int wrp  = tid >> 5;
    int p    = blockIdx.x * blockDim.x + tid;

    __shared__ float4 tb[OMAX];
    __shared__ float  ta_s[OMAX];
    __shared__ unsigned long long wkey[8 * OMAX];

    if (tid < O) {
        const float* t = targets + ((long)b * O + tid) * 5;
        float4 v = make_float4(t[0], t[1], t[2], t[3]);
        tb[tid]   = v;
        ta_s[tid] = (v.z - v.x) * (v.w - v.y);
    }
    __syncthreads();

    bool valid = (p < P);
    float4 pr = valid ? reinterpret_cast<const float4*>(priors)[p]
                      : make_float4(0.f, 0.f, 1.f, 1.f);
    float px0 = pr.x - pr.z * 0.5f;
    float py0 = pr.y - pr.w * 0.5f;
    float px1 = pr.x + pr.z * 0.5f;
    float py1 = pr.y + pr.w * 0.5f;
    float pa  = (px1 - px0) * (py1 - py0);

    float best = -1.0f;
    int   besto = 0;

    #pragma unroll 4
    for (int o = 0; o < O; o++) {
        float iou = valid ? iou_one(tb[o], ta_s[o], px0, py0, px1, py1, pa) : 0.0f;
        if (iou > best) { best = iou; besto = o; }

        unsigned ib = valid ? __float_as_uint(iou) : 0u;
        unsigned m  = __reduce_max_sync(0xffffffffu, ib);
        unsigned win = __ballot_sync(0xffffffffu, ib == m);
        if (lane == (int)(__ffs(win) - 1)) {
            wkey[wrp * OMAX + o] =
                ((unsigned long long)m << 32) |
                (unsigned int)(~(unsigned int)p);
        }
    }

    float ll = 0.0f, cp = 0.0f;
    int np = 0;
    if (valid) {
        long ip = (long)b * P + p;
        int ct = (best >= OVERLAP_T) ? 1 : 0;
        float2 c = reinterpret_cast<const float2*>(conf)[ip];
        float lse = lse2(c);
        float ce_neg;
        if (ct) {
            np = 1;
            cp = lse - c.y;
            ce_neg = 0.0f;
            float4 l = reinterpret_cast<const float4*>(loc)[ip];
            ll = sl1_of(l, pr, tb[besto]);
        } else {
            ce_neg = lse - c.x;
        }
        g_ce[ip] = ce_neg;
    }

    #pragma unroll
    for (int off = 16; off; off >>= 1) {
        ll += __shfl_xor_sync(0xffffffffu, ll, off);
        cp += __shfl_xor_sync(0xffffffffu, cp, off);
        np += __shfl_xor_sync(0xffffffffu, np, off);
    }
    __shared__ float wl[8], wc[8];
    __shared__ int   wn[8];
    if (lane == 0) { wl[wrp] = ll; wc[wrp] = cp; wn[wrp] = np; }
    __syncthreads();
    if (tid == 0) {
        float a = 0.f, cc = 0.f; int nn = 0;
        #pragma unroll
        for (int w = 0; w < 8; w++) { a += wl[w]; cc += wc[w]; nn += wn[w]; }
        int bi = b * gridDim.x + blockIdx.x;
        g_pl[bi] = a; g_pc[bi] = cc; g_pn[bi] = nn;
    }
    if (tid < O) {
        unsigned long long bk = wkey[tid];
        #pragma unroll
        for (int w = 1; w < 8; w++) {
            unsigned long long k2 = wkey[w * OMAX + tid];
            if (k2 > bk) bk = k2;
        }
        atomicMax(&g_key[b * OMAX + tid], bk);
    }
}

// ---------------------------------------------------------------------------
// Fused fixup + radix-select top-k + (last block) final reduction.
// Passes A/B process 2×uint4 per iteration for MLP.
// ---------------------------------------------------------------------------
__global__ __launch_bounds__(1024)
void k_topk(const float* __restrict__ loc,
            const float* __restrict__ conf,
            const float* __restrict__ priors,
            const float* __restrict__ targets,
            float* __restrict__ out,
            int P, int O, int nb, int B) {
    extern __shared__ unsigned dyn[];
    unsigned* sd   = dyn;
    unsigned* buf1 = dyn + P;
    unsigned* buf2 = buf1 + BUF1;
    unsigned* hist = buf2 + BUF2;
    unsigned* sfx  = hist + 2048;

    __shared__ unsigned csum[64], cadd[64];
    __shared__ int      ps[OMAX];
    __shared__ float    fred[32];
    __shared__ int      ired[32];
    __shared__ double   dredA[32], dredC[32];
    __shared__ float    s_dl, s_dc;
    __shared__ int      s_dn, s_np, s_krem, s_chosen, s_last;
    __shared__ unsigned s_above, s_cnt1, s_cnt2;

    int b    = blockIdx.x;
    int tid  = threadIdx.x;
    int lane = tid & 31;
    int wrp  = tid >> 5;

    if (tid == 0) { s_dl = 0.f; s_dc = 0.f; s_dn = 0; s_cnt1 = 0u; s_cnt2 = 0u; }
    int np = 0;
    for (int j = tid; j < nb; j += 1024) np += g_pn[b * nb + j];
    #pragma unroll
    for (int off = 16; off; off >>= 1) np += __shfl_xor_sync(0xffffffffu, np, off);
    if (lane == 0) ired[wrp] = np;
    if (tid < O) {
        ps[tid] = (int)(~(unsigned int)(g_key[b * OMAX + tid] & 0xffffffffull));
        g_key[b * OMAX + tid] = 0ull;
    }
    __syncthreads();
    if (tid == 0) {
        int acc0 = 0;
        #pragma unroll
        for (int w = 0; w < 32; w++) acc0 += ired[w];
        s_np = acc0;
    }

    if (tid < O) {
        int p = ps[tid];
        bool dup = false;
        for (int o2 = tid + 1; o2 < O; o2++) if (ps[o2] == p) dup = true;
        if (!dup) {
            float4 pr = reinterpret_cast<const float4*>(priors)[p];
            float px0 = pr.x - pr.z * 0.5f;
            float py0 = pr.y - pr.w * 0.5f;
            float px1 = pr.x + pr.z * 0.5f;
            float py1 = pr.y + pr.w * 0.5f;
            float pa  = (px1 - px0) * (py1 - py0);

            float best = -1.0f; int bo = 0;
            for (int oo = 0; oo < O; oo++) {
                const float* tt = targets + ((long)b * O + oo) * 5;
                float4 t = make_float4(tt[0], tt[1], tt[2], tt[3]);
                float ta = (t.z - t.x) * (t.w - t.y);
                float iou = iou_one(t, ta, px0, py0, px1, py1, pa);
                if (iou > best) { best = iou; bo = oo; }
            }
            int ct = (best >= OVERLAP_T) ? 1 : 0;

            long ip = (long)b * P + p;
            float4 l = reinterpret_cast<const float4*>(loc)[ip];
            const float* tf = targets + ((long)b * O + tid) * 5;
            float4 tnew = make_float4(tf[0], tf[1], tf[2], tf[3]);
            float sl_new = sl1_of(l, pr, tnew);

            if (ct) {
                const float* to = targets + ((long)b * O + bo) * 5;
                float4 told = make_float4(to[0], to[1], to[2], to[3]);
                atomicAdd(&s_dl, sl_new - sl1_of(l, pr, told));
            } else {
                float2 c = reinterpret_cast<const float2*>(conf)[ip];
                float lse = lse2(c);
                atomicAdd(&s_dl, sl_new);
                atomicAdd(&s_dc, lse - c.y);
                atomicAdd(&s_dn, 1);
                g_ce[ip] = 0.0f;
            }
        }
    }
    for (int i = tid; i < 2048; i += 1024) hist[i] = 0u;
    __syncthreads();

    int npos = s_np + s_dn;
    int k = 3 * npos; if (k > P - 1) k = P - 1;
    if (tid == 0) {
        g_npos[b] = npos;
        g_fl[b] = s_dl;
        g_fc[b] = s_dc;
        s_krem = k;
    }
    __syncthreads();

    float acc = 0.0f;
    int c1 = 0, c2 = 0, c3 = 0;

    if (k > 0) {
        const uint4* v4 = reinterpret_cast<const uint4*>(g_ce + (long)b * P);
        uint4* sd4 = reinterpret_cast<uint4*>(sd);
        int P4 = P >> 2;

        // ---- pass A: 2×uint4 per iteration (MLP 8) ----
        for (int i = tid; i < P4; i += 2048) {
            uint4 ua = v4[i];
            int i2 = i + 1024;
            bool h2 = (i2 < P4);
            uint4 ub = h2 ? v4[i2] : make_uint4(0u, 0u, 0u, 0u);
            sd4[i] = ua;
            if (h2) sd4[i2] = ub;
            atomicAdd(&hist[ua.x >> 21], 1u);
            atomicAdd(&hist[ua.y >> 21], 1u);
            atomicAdd(&hist[ua.z >> 21], 1u);
            atomicAdd(&hist[ua.w >> 21], 1u);
            if (h2) {
                atomicAdd(&hist[ub.x >> 21], 1u);
                atomicAdd(&hist[ub.y >> 21], 1u);
                atomicAdd(&hist[ub.z >> 21], 1u);
                atomicAdd(&hist[ub.w >> 21], 1u);
            }
        }
        __syncthreads();

        #define SELECT_BIN(NBINS)                                               \
        {                                                                       \
            for (int i = tid; i < (NBINS); i += 1024) {                         \
                unsigned val = hist[i];                                         \
                _Pragma("unroll")                                               \
                for (int off = 1; off < 32; off <<= 1) {                        \
                    unsigned t2 = __shfl_down_sync(0xffffffffu, val, off);      \
                    if (lane + off < 32) val += t2;                             \
                }                                                               \
                sfx[i] = val;                                                   \
                if (lane == 0) csum[i >> 5] = val;                              \
            }                                                                   \
            __syncthreads();                                                    \
            int nch = (NBINS) >> 5;                                             \
            if (tid < nch) {                                                    \
                unsigned add = 0;                                               \
                for (int j = tid + 1; j < nch; j++) add += csum[j];             \
                cadd[tid] = add;                                                \
            }                                                                   \
            __syncthreads();                                                    \
            for (int i = tid; i < (NBINS); i += 1024) sfx[i] += cadd[i >> 5];   \
            __syncthreads();                                                    \
            int krem = s_krem;                                                  \
            for (int i = tid; i < (NBINS); i += 1024) {                         \
                unsigned s  = sfx[i];                                           \
                unsigned sn = (i + 1 < (NBINS)) ? sfx[i + 1] : 0u;              \
                if ((int)s >= krem && (int)sn < krem) {                         \
                    s_chosen = i; s_above = sn;                                 \
                }                                                               \
            }                                                                   \
            __syncthreads();                                                    \
            if (tid == 0) s_krem -= (int)s_above;                               \
        }

        SELECT_BIN(2048);
        c1 = s_chosen;
        for (int i = tid; i < 2048; i += 1024) hist[i] = 0u;
        __syncthreads();

        // ---- pass B: 2×uint4 per iteration; bins>c1 → acc; ==c1 → compact ----
        for (int i = tid; i < P4; i += 2048) {
            uint4 ua = sd4[i];
            int i2 = i + 1024;
            bool h2 = (i2 < P4);
            uint4 ub = h2 ? sd4[i2] : make_uint4(0u, 0u, 0u, 0u);
            #pragma unroll
            for (int e = 0; e < 8; e++) {
                if (e >= 4 && !h2) break;
                unsigned ue;
                switch (e) {
                    case 0: ue = ua.x; break;
                    case 1: ue = ua.y; break;
                    case 2: ue = ua.z; break;
                    case 3: ue = ua.w; break;
                    case 4: ue = ub.x; break;
                    case 5: ue = ub.y; break;
                    case 6: ue = ub.z; break;
                    default: ue = ub.w; break;
                }
                int bin = (int)(ue >> 21);
                if (bin > c1) acc += __uint_as_float(ue);
                else if (bin == c1) {
                    unsigned pos = atomicAdd(&s_cnt1, 1u);
                    if (pos < BUF1) buf1[pos] = ue;
                    atomicAdd(&hist[(ue >> 10) & 0x7FFu], 1u);
                }
            }
        }
        __syncthreads();

        SELECT_BIN(2048);
        c2 = s_chosen;
        unsigned S1 = s_cnt1;
        if (tid < 1024) hist[tid] = 0u;
        __syncthreads();

        if (S1 <= BUF1) {
            for (unsigned i = tid; i < S1; i += 1024) {
                unsigned u = buf1[i];
                int bin2 = (int)((u >> 10) & 0x7FFu);
                if (bin2 > c2) acc += __uint_as_float(u);
                else if (bin2 == c2) {
                    unsigned pos = atomicAdd(&s_cnt2, 1u);
                    if (pos < BUF2) buf2[pos] = u;
                    atomicAdd(&hist[u & 0x3FFu], 1u);
                }
            }
        } else {
            for (int i = tid; i < P; i += 1024) {
                unsigned u = sd[i];
                if ((int)(u >> 21) != c1) continue;
                int bin2 = (int)((u >> 10) & 0x7FFu);
                if (bin2 > c2) acc += __uint_as_float(u);
                else if (bin2 == c2) {
                    unsigned pos = atomicAdd(&s_cnt2, 1u);
                    if (pos < BUF2) buf2[pos] = u;
                    atomicAdd(&hist[u & 0x3FFu], 1u);
                }
            }
        }
        __syncthreads();

        SELECT_BIN(1024);
        c3 = s_chosen;
        unsigned S2 = s_cnt2;
        __syncthreads();

        if (S2 <= BUF2) {
            for (unsigned i = tid; i < S2; i += 1024) {
                unsigned u = buf2[i];
                if ((int)(u & 0x3FFu) > c3) acc += __uint_as_float(u);
            }
        } else {
            for (int i = tid; i < P; i += 1024) {
                unsigned u = sd[i];
                if ((int)(u >> 21) == c1 && (int)((u >> 10) & 0x7FFu) == c2 &&
                    (int)(u & 0x3FFu) > c3)
                    acc += __uint_as_float(u);
            }
        }

        #pragma unroll
        for (int off = 16; off; off >>= 1)
            acc += __shfl_xor_sync(0xffffffffu, acc, off);
        if (lane == 0) fred[wrp] = acc;
        __syncthreads();
        if (tid == 0) {
            float tot = 0.f;
            #pragma unroll
            for (int w = 0; w < 32; w++) tot += fred[w];
            unsigned tbits = ((unsigned)c1 << 21) | ((unsigned)c2 << 10) | (unsigned)c3;
            g_cneg[b] = tot + (float)s_krem * __uint_as_float(tbits);
        }
    } else {
        if (tid == 0) g_cneg[b] = 0.0f;
    }

    if (tid == 0) {
        __threadfence();
        unsigned old = atomicAdd(&g_done, 1u);
        s_last = (old == (unsigned)(B - 1));
    }
    __syncthreads();
    if (!s_last) return;
    __threadfence();

    double a = 0.0, cc = 0.0;
    int n = 0;
    int tot = B * nb;
    for (int i = tid; i < tot; i += 1024) { a += (double)g_pl[i]; cc += (double)g_pc[i]; }
    for (int i = tid; i < B; i += 1024) {
        a  += (double)g_fl[i];
        cc += (double)g_fc[i] + (double)g_cneg[i];
        n  += g_npos[i];
    }
    #pragma unroll
    for (int off = 16; off; off >>= 1) {
        a  += __shfl_xor_sync(0xffffffffu, a, off);
        cc += __shfl_xor_sync(0xffffffffu, cc, off);
        n  += __shfl_xor_sync(0xffffffffu, n, off);
    }
    if (lane == 0) { dredA[wrp] = a; dredC[wrp] = cc; ired[wrp] = n; }
    __syncthreads();
    if (tid == 0) {
        double ta = 0.0, tc = 0.0; int tn = 0;
        #pragma unroll
        for (int w = 0; w < 32; w++) { ta += dredA[w]; tc += dredC[w]; tn += ired[w]; }
        double N = (double)tn;
        if (N < 1.0) N = 1.0;
        out[0] = (float)(ta / N);
        out[1] = (float)(tc / N);
        g_done = 0u;
    }
}

extern "C" void kernel_launch(void* const* d_in, const int* in_sizes, int n_in,
                              void* d_out, int out_size) {
    const float* loc     = (const float*)d_in[0];
    const float* conf    = (const float*)d_in[1];
    const float* priors  = (const float*)d_in[2];
    const float* targets = (const float*)d_in[3];
    float* out = (float*)d_out;

    int P = in_sizes[2] / 4;
    int B = in_sizes[0] / (P * 4);
    int O = in_sizes[3] / (B * 5);

    static int smem_set = 0;
    if (!smem_set) {
        cudaFuncSetAttribute(k_topk, cudaFuncAttributeMaxDynamicSharedMemorySize,
                             DSMEM_WORDS * 4);
        smem_set = 1;
    }

    int nb;
    if (O == 16 && (P % 1024) == 0) {
        nb = P / 1024;
        dim3 grid(nb, B);
        k_main4<<<grid, 256>>>(loc, conf, priors, targets, P);
    } else {
        nb = (P + 255) / 256;
        dim3 grid(nb, B);
        k_main1<<<grid, 256>>>(loc, conf, priors, targets, P, O);
    }
    k_topk<<<B, 1024, DSMEM_WORDS * 4>>>(
        loc, conf, priors, targets, out, P, O, nb, B);
}

// round 17
// speedup vs baseline: 1.7495x; 1.0317x over previous
#include <cuda_runtime.h>

#define OVERLAP_T 0.5f
#define VAR0 0.1f
#define VAR1 0.2f

#define BMAX 64
#define PMAX 32768
#define OMAX 64
#define NBLK (PMAX/256)
#define BUF1 8192
#define BUF2 1024
// dynamic smem (uints): sd[PMAX] | buf1 | buf2 | histA[2048] | histB[2048]
#define DSMEM_WORDS (PMAX + BUF1 + BUF2 + 2048 + 2048)

// Scratch (static device arrays; zero-initialized at load; each run leaves
// g_key/g_done zeroed again so graph replays see clean state)
__device__ float               g_ce[BMAX * PMAX];
__device__ unsigned long long  g_key[BMAX * OMAX];
__device__ int                 g_npos[BMAX];
__device__ float               g_pl[BMAX * NBLK];
__device__ float               g_pc[BMAX * NBLK];
__device__ int                 g_pn[BMAX * NBLK];
__device__ float               g_fl[BMAX];
__device__ float               g_fc[BMAX];
__device__ float               g_cneg[BMAX];
__device__ unsigned            g_done;

__device__ __forceinline__ float iou_one(float4 t, float ta,
                                         float px0, float py0, float px1, float py1,
                                         float pa) {
    float lx = fmaxf(t.x, px0), ly = fmaxf(t.y, py0);
    float rx = fminf(t.z, px1), ry = fminf(t.w, py1);
    float w = fmaxf(rx - lx, 0.0f), h = fmaxf(ry - ly, 0.0f);
    float inter = w * h;
    float den = ta + pa - inter;
    return __fdividef(inter, den);
}

__device__ __forceinline__ float sl1_of(float4 l, float4 pr, float4 t) {
    float gcx = ((t.x + t.z) * 0.5f - pr.x) / (VAR0 * pr.z);
    float gcy = ((t.y + t.w) * 0.5f - pr.y) / (VAR0 * pr.w);
    float gw  = __logf((t.z - t.x) / pr.z) * (1.0f / VAR1);
    float gh  = __logf((t.w - t.y) / pr.w) * (1.0f / VAR1);
    float d0 = l.x - gcx, d1 = l.y - gcy, d2 = l.z - gw, d3 = l.w - gh;
    float a0 = fabsf(d0), a1 = fabsf(d1), a2 = fabsf(d2), a3 = fabsf(d3);
    float s0 = (a0 < 1.0f) ? 0.5f * d0 * d0 : a0 - 0.5f;
    float s1 = (a1 < 1.0f) ? 0.5f * d1 * d1 : a1 - 0.5f;
    float s2 = (a2 < 1.0f) ? 0.5f * d2 * d2 : a2 - 0.5f;
    float s3 = (a3 < 1.0f) ? 0.5f * d3 * d3 : a3 - 0.5f;
    return (s0 + s1) + (s2 + s3);
}

__device__ __forceinline__ float lse2(float2 c) {
    float mx = fmaxf(c.x, c.y);
    float mn = fminf(c.x, c.y);
    return mx + __logf(1.0f + __expf(mn - mx));
}

// ---------------------------------------------------------------------------
// Quad match + loss (unchanged from measured 67.6µs version).
// ---------------------------------------------------------------------------
__global__ __launch_bounds__(256)
void k_main4(const float* __restrict__ loc,
             const float* __restrict__ conf,
             const float* __restrict__ priors,
             const float* __restrict__ targets,
             int P) {
    const int O = 16;
    int b    = blockIdx.y;
    int tid  = threadIdx.x;
    int lane = tid & 31;
    int wrp  = tid >> 5;
    int t4   = blockIdx.x * blockDim.x + tid;
    int p0   = 4 * t4;

    __shared__ float4 tb[O];
    __shared__ float  ta_s[O];
    __shared__ unsigned long long wkey[8 * O];

    if (tid < O) {
        const float* t = targets + ((long)b * O + tid) * 5;
        float4 v = make_float4(t[0], t[1], t[2], t[3]);
        tb[tid]   = v;
        ta_s[tid] = (v.z - v.x) * (v.w - v.y);
    }
    __syncthreads();

    float x0[4], y0[4], x1[4], y1[4], ar[4];
    float4 prq[4];
    #pragma unroll
    for (int q = 0; q < 4; q++) {
        prq[q] = reinterpret_cast<const float4*>(priors)[p0 + q];
        x0[q] = prq[q].x - prq[q].z * 0.5f;
        y0[q] = prq[q].y - prq[q].w * 0.5f;
        x1[q] = prq[q].x + prq[q].z * 0.5f;
        y1[q] = prq[q].y + prq[q].w * 0.5f;
        ar[q] = (x1[q] - x0[q]) * (y1[q] - y0[q]);
    }

    float bestq[4] = {-1.f, -1.f, -1.f, -1.f};
    int   boq[4]   = {0, 0, 0, 0};

    #pragma unroll 4
    for (int o = 0; o < O; o++) {
        float4 t = tb[o];
        float ta = ta_s[o];
        float iou[4];
        #pragma unroll
        for (int q = 0; q < 4; q++) {
            iou[q] = iou_one(t, ta, x0[q], y0[q], x1[q], y1[q], ar[q]);
            if (iou[q] > bestq[q]) { bestq[q] = iou[q]; boq[q] = o; }
        }
        unsigned cur = __float_as_uint(iou[0]);
        int sel = 0;
        #pragma unroll
        for (int q = 1; q < 4; q++) {
            unsigned ibq = __float_as_uint(iou[q]);
            if (ibq > cur) { cur = ibq; sel = q; }
        }
        unsigned m   = __reduce_max_sync(0xffffffffu, cur);
        unsigned win = __ballot_sync(0xffffffffu, cur == m);
        if (lane == (int)(__ffs(win) - 1)) {
            wkey[wrp * O + o] =
                ((unsigned long long)m << 32) |
                (unsigned int)(~(unsigned int)(p0 + sel));
        }
    }

    long ipb = (long)b * P;
    const float4* c4p = reinterpret_cast<const float4*>(conf) + (ipb >> 1) + 2 * t4;
    float4 c01 = c4p[0];
    float4 c23 = c4p[1];
    float2 cq[4] = { make_float2(c01.x, c01.y), make_float2(c01.z, c01.w),
                     make_float2(c23.x, c23.y), make_float2(c23.z, c23.w) };

    float ll = 0.0f, cp = 0.0f;
    float ce[4];
    int np = 0;
    #pragma unroll
    for (int q = 0; q < 4; q++) {
        float lse = lse2(cq[q]);
        if (bestq[q] >= OVERLAP_T) {
            np += 1;
            cp += lse - cq[q].y;
            ce[q] = 0.0f;
            float4 l = reinterpret_cast<const float4*>(loc)[ipb + p0 + q];
            ll += sl1_of(l, prq[q], tb[boq[q]]);
        } else {
            ce[q] = lse - cq[q].x;
        }
    }
    reinterpret_cast<float4*>(g_ce)[(ipb >> 2) + t4] =
        make_float4(ce[0], ce[1], ce[2], ce[3]);

    #pragma unroll
    for (int off = 16; off; off >>= 1) {
        ll += __shfl_xor_sync(0xffffffffu, ll, off);
        cp += __shfl_xor_sync(0xffffffffu, cp, off);
        np += __shfl_xor_sync(0xffffffffu, np, off);
    }
    __shared__ float wl[8], wc[8];
    __shared__ int   wn[8];
    if (lane == 0) { wl[wrp] = ll; wc[wrp] = cp; wn[wrp] = np; }
    __syncthreads();
    if (tid == 0) {
        float a = 0.f, cc = 0.f; int nn = 0;
        #pragma unroll
        for (int w = 0; w < 8; w++) { a += wl[w]; cc += wc[w]; nn += wn[w]; }
        int bi = b * gridDim.x + blockIdx.x;
        g_pl[bi] = a; g_pc[bi] = cc; g_pn[bi] = nn;
    }
    if (tid < O) {
        unsigned long long bk = wkey[tid];
        #pragma unroll
        for (int w = 1; w < 8; w++) {
            unsigned long long k2 = wkey[w * O + tid];
            if (k2 > bk) bk = k2;
        }
        atomicMax(&g_key[b * OMAX + tid], bk);
    }
}

// ---------------------------------------------------------------------------
// Generic fallback (one prior/thread) for O != 16 or P % 1024 != 0.
// ---------------------------------------------------------------------------
__global__ __launch_bounds__(256)
void k_main1(const float* __restrict__ loc,
             const float* __restrict__ conf,
             const float* __restrict__ priors,
             const float* __restrict__ targets,
             int P, int O) {
    int b    = blockIdx.y;
    int tid  = threadIdx.x;
    int lane = tid & 31;
    int wrp  = tid >> 5;
    int p    = blockIdx.x * blockDim.x + tid;

    __shared__ float4 tb[OMAX];
    __shared__ float  ta_s[OMAX];
    __shared__ unsigned long long wkey[8 * OMAX];

    if (tid < O) {
        const float* t = targets + ((long)b * O + tid) * 5;
        float4 v = make_float4(t[0], t[1], t[2], t[3]);
        tb[tid]   = v;
        ta_s[tid] = (v.z - v.x) * (v.w - v.y);
    }
    __syncthreads();

    bool valid = (p < P);
    float4 pr = valid ? reinterpret_cast<const float4*>(priors)[p]
                      : make_float4(0.f, 0.f, 1.f, 1.f);
    float px0 = pr.x - pr.z * 0.5f;
    float py0 = pr.y - pr.w * 0.5f;
    float px1 = pr.x + pr.z * 0.5f;
    float py1 = pr.y + pr.w * 0.5f;
    float pa  = (px1 - px0) * (py1 - py0);

    float best = -1.0f;
    int   besto = 0;

    #pragma unroll 4
    for (int o = 0; o < O; o++) {
        float iou = valid ? iou_one(tb[o], ta_s[o], px0, py0, px1, py1, pa) : 0.0f;
        if (iou > best) { best = iou; besto = o; }

        unsigned ib = valid ? __float_as_uint(iou) : 0u;
        unsigned m  = __reduce_max_sync(0xffffffffu, ib);
        unsigned win = __ballot_sync(0xffffffffu, ib == m);
        if (lane == (int)(__ffs(win) - 1)) {
            wkey[wrp * OMAX + o] =
                ((unsigned long long)m << 32) |
                (unsigned int)(~(unsigned int)p);
        }
    }

    float ll = 0.0f, cp = 0.0f;
    int np = 0;
    if (valid) {
        long ip = (long)b * P + p;
        int ct = (best >= OVERLAP_T) ? 1 : 0;
        float2 c = reinterpret_cast<const float2*>(conf)[ip];
        float lse = lse2(c);
        float ce_neg;
        if (ct) {
            np = 1;
            cp = lse - c.y;
            ce_neg = 0.0f;
            float4 l = reinterpret_cast<const float4*>(loc)[ip];
            ll = sl1_of(l, pr, tb[besto]);
        } else {
            ce_neg = lse - c.x;
        }
        g_ce[ip] = ce_neg;
    }

    #pragma unroll
    for (int off = 16; off; off >>= 1) {
        ll += __shfl_xor_sync(0xffffffffu, ll, off);
        cp += __shfl_xor_sync(0xffffffffu, cp, off);
        np += __shfl_xor_sync(0xffffffffu, np, off);
    }
    __shared__ float wl[8], wc[8];
    __shared__ int   wn[8];
    if (lane == 0) { wl[wrp] = ll; wc[wrp] = cp; wn[wrp] = np; }
    __syncthreads();
    if (tid == 0) {
        float a = 0.f, cc = 0.f; int nn = 0;
        #pragma unroll
        for (int w = 0; w < 8; w++) { a += wl[w]; cc += wc[w]; nn += wn[w]; }
        int bi = b * gridDim.x + blockIdx.x;
        g_pl[bi] = a; g_pc[bi] = cc; g_pn[bi] = nn;
    }
    if (tid < O) {
        unsigned long long bk = wkey[tid];
        #pragma unroll
        for (int w = 1; w < 8; w++) {
            unsigned long long k2 = wkey[w * OMAX + tid];
            if (k2 > bk) bk = k2;
        }
        atomicMax(&g_key[b * OMAX + tid], bk);
    }
}

// ---------------------------------------------------------------------------
// Fused fixup + radix-select top-k + (last block) final reduction.
// New 3-barrier SELECT3: register-resident suffix scan, warp-0 csum scan
// overlapped with next-hist zeroing (ping-pong), no sfx array.
// ---------------------------------------------------------------------------
__global__ __launch_bounds__(1024)
void k_topk(const float* __restrict__ loc,
            const float* __restrict__ conf,
            const float* __restrict__ priors,
            const float* __restrict__ targets,
            float* __restrict__ out,
            int P, int O, int nb, int B) {
    extern __shared__ unsigned dyn[];
    unsigned* sd    = dyn;
    unsigned* buf1  = dyn + P;
    unsigned* buf2  = buf1 + BUF1;
    unsigned* histA = buf2 + BUF2;    // 2048
    unsigned* histB = histA + 2048;   // 2048

    __shared__ unsigned csum[32], cadd[32];
    __shared__ int      ps[OMAX];
    __shared__ float    fred[32];
    __shared__ int      ired[32];
    __shared__ double   dredA[32], dredC[32];
    __shared__ float    s_dl, s_dc;
    __shared__ int      s_dn, s_np, s_krem, s_chosen, s_last;
    __shared__ unsigned s_cnt1, s_cnt2;

    int b    = blockIdx.x;
    int tid  = threadIdx.x;
    int lane = tid & 31;
    int wrp  = tid >> 5;

    // ---------------- fixup prologue ----------------
    if (tid == 0) { s_dl = 0.f; s_dc = 0.f; s_dn = 0; s_cnt1 = 0u; s_cnt2 = 0u; }
    int np = 0;
    for (int j = tid; j < nb; j += 1024) np += g_pn[b * nb + j];
    #pragma unroll
    for (int off = 16; off; off >>= 1) np += __shfl_xor_sync(0xffffffffu, np, off);
    if (lane == 0) ired[wrp] = np;
    if (tid < O) {
        ps[tid] = (int)(~(unsigned int)(g_key[b * OMAX + tid] & 0xffffffffull));
        g_key[b * OMAX + tid] = 0ull;
    }
    __syncthreads();
    if (tid == 0) {
        int acc0 = 0;
        #pragma unroll
        for (int w = 0; w < 32; w++) acc0 += ired[w];
        s_np = acc0;
    }

    if (tid < O) {
        int p = ps[tid];
        bool dup = false;
        for (int o2 = tid + 1; o2 < O; o2++) if (ps[o2] == p) dup = true;
        if (!dup) {
            float4 pr = reinterpret_cast<const float4*>(priors)[p];
            float px0 = pr.x - pr.z * 0.5f;
            float py0 = pr.y - pr.w * 0.5f;
            float px1 = pr.x + pr.z * 0.5f;
            float py1 = pr.y + pr.w * 0.5f;
            float pa  = (px1 - px0) * (py1 - py0);

            float best = -1.0f; int bo = 0;
            for (int oo = 0; oo < O; oo++) {
                const float* tt = targets + ((long)b * O + oo) * 5;
                float4 t = make_float4(tt[0], tt[1], tt[2], tt[3]);
                float ta = (t.z - t.x) * (t.w - t.y);
                float iou = iou_one(t, ta, px0, py0, px1, py1, pa);
                if (iou > best) { best = iou; bo = oo; }
            }
            int ct = (best >= OVERLAP_T) ? 1 : 0;

            long ip = (long)b * P + p;
            float4 l = reinterpret_cast<const float4*>(loc)[ip];
            const float* tf = targets + ((long)b * O + tid) * 5;
            float4 tnew = make_float4(tf[0], tf[1], tf[2], tf[3]);
            float sl_new = sl1_of(l, pr, tnew);

            if (ct) {
                const float* to = targets + ((long)b * O + bo) * 5;
                float4 told = make_float4(to[0], to[1], to[2], to[3]);
                atomicAdd(&s_dl, sl_new - sl1_of(l, pr, told));
            } else {
                float2 c = reinterpret_cast<const float2*>(conf)[ip];
                float lse = lse2(c);
                atomicAdd(&s_dl, sl_new);
                atomicAdd(&s_dc, lse - c.y);
                atomicAdd(&s_dn, 1);
                g_ce[ip] = 0.0f;   // visible to pass A via __syncthreads
            }
        }
    }
    for (int i = tid; i < 2048; i += 1024) histA[i] = 0u;
    __syncthreads();

    int npos = s_np + s_dn;
    int k = 3 * npos; if (k > P - 1) k = P - 1;
    if (tid == 0) {
        g_npos[b] = npos;
        g_fl[b] = s_dl;
        g_fc[b] = s_dc;
        s_krem = k;
    }
    __syncthreads();

    float acc = 0.0f;
    int c1 = 0, c2 = 0, c3 = 0;

    if (k > 0) {
        const uint4* v4 = reinterpret_cast<const uint4*>(g_ce + (long)b * P);
        uint4* sd4 = reinterpret_cast<uint4*>(sd);
        int P4 = P >> 2;

        // ---- pass A: load (2×uint4, MLP 8) + round-1 histogram ----
        for (int i = tid; i < P4; i += 2048) {
            uint4 ua = v4[i];
            int i2 = i + 1024;
            bool h2 = (i2 < P4);
            uint4 ub = h2 ? v4[i2] : make_uint4(0u, 0u, 0u, 0u);
            sd4[i] = ua;
            if (h2) sd4[i2] = ub;
            atomicAdd(&histA[ua.x >> 21], 1u);
            atomicAdd(&histA[ua.y >> 21], 1u);
            atomicAdd(&histA[ua.z >> 21], 1u);
            atomicAdd(&histA[ua.w >> 21], 1u);
            if (h2) {
                atomicAdd(&histB[0], 0u);  // no-op keep histB symbol live
                atomicAdd(&histA[ub.x >> 21], 1u);
                atomicAdd(&histA[ub.y >> 21], 1u);
                atomicAdd(&histA[ub.z >> 21], 1u);
                atomicAdd(&histA[ub.w >> 21], 1u);
            }
        }
        __syncthreads();

        // 3-barrier select over NBINS bins (BPT = NBINS/1024 ∈ {1,2}).
        // While warp 0 scans csum, warps 1..31 zero ZN entries of ZH.
        #define SELECT3(NBINS, HIST, ZH, ZN)                                    \
        {                                                                       \
            const int BPT = (NBINS) / 1024;                                     \
            unsigned hh[2] = {0u, 0u};                                          \
            unsigned psum = 0;                                                  \
            _Pragma("unroll")                                                   \
            for (int j = 0; j < BPT; j++) {                                     \
                hh[j] = (HIST)[tid * BPT + j];                                  \
                psum += hh[j];                                                  \
            }                                                                   \
            int krem = s_krem;                                                  \
            unsigned incl = psum;                                               \
            _Pragma("unroll")                                                   \
            for (int off = 1; off < 32; off <<= 1) {                            \
                unsigned tt = __shfl_down_sync(0xffffffffu, incl, off);         \
                if (lane + off < 32) incl += tt;                                \
            }                                                                   \
            if (lane == 0) csum[wrp] = incl;                                    \
            __syncthreads();                                                    \
            if (wrp == 0) {                                                     \
                unsigned cv = csum[lane];                                       \
                unsigned ci = cv;                                               \
                _Pragma("unroll")                                               \
                for (int off = 1; off < 32; off <<= 1) {                        \
                    unsigned tt = __shfl_down_sync(0xffffffffu, ci, off);       \
                    if (lane + off < 32) ci += tt;                              \
                }                                                               \
                cadd[lane] = ci - cv;                                           \
            } else if ((ZN) > 0) {                                              \
                for (int i = tid - 32; i < (ZN); i += 992) (ZH)[i] = 0u;        \
            }                                                                   \
            __syncthreads();                                                    \
            {                                                                   \
                unsigned run = cadd[wrp] + (incl - psum);                       \
                _Pragma("unroll")                                               \
                for (int j = BPT - 1; j >= 0; j--) {                            \
                    unsigned sfxj = run + hh[j];                                \
                    if ((int)sfxj >= krem && (int)run < krem) {                 \
                        s_chosen = tid * BPT + j;                               \
                        s_krem = krem - (int)run;                               \
                    }                                                           \
                    run = sfxj;                                                 \
                }                                                               \
            }                                                                   \
            __syncthreads();                                                    \
        }

        SELECT3(2048, histA, histB, 2048);
        c1 = s_chosen;

        // ---- pass B: bins>c1 → acc; ==c1 → compact buf1 + hist2 (histB) ----
        for (int i = tid; i < P4; i += 1024) {
            uint4 u = sd4[i];
            #pragma unroll
            for (int e = 0; e < 4; e++) {
                unsigned ue = (e == 0) ? u.x : (e == 1) ? u.y : (e == 2) ? u.z : u.w;
                int bin = (int)(ue >> 21);
                if (bin > c1) acc += __uint_as_float(ue);
                else if (bin == c1) {
                    unsigned pos = atomicAdd(&s_cnt1, 1u);
                    if (pos < BUF1) buf1[pos] = ue;
                    atomicAdd(&histB[(ue >> 10) & 0x7FFu], 1u);
                }
            }
        }
        __syncthreads();

        SELECT3(2048, histB, histA, 1024);
        c2 = s_chosen;
        unsigned S1 = s_cnt1;

        // ---- pass C: survivors bins2>c2 → acc, ==c2 → buf2 + hist3 (histA) ----
        if (S1 <= BUF1) {
            for (unsigned i = tid; i < S1; i += 1024) {
                unsigned u = buf1[i];
                int bin2 = (int)((u >> 10) & 0x7FFu);
                if (bin2 > c2) acc += __uint_as_float(u);
                else if (bin2 == c2) {
                    unsigned pos = atomicAdd(&s_cnt2, 1u);
                    if (pos < BUF2) buf2[pos] = u;
                    atomicAdd(&histA[u & 0x3FFu], 1u);
                }
            }
        } else {
            for (int i = tid; i < P; i += 1024) {
                unsigned u = sd[i];
                if ((int)(u >> 21) != c1) continue;
                int bin2 = (int)((u >> 10) & 0x7FFu);
                if (bin2 > c2) acc += __uint_as_float(u);
                else if (bin2 == c2) {
                    unsigned pos = atomicAdd(&s_cnt2, 1u);
                    if (pos < BUF2) buf2[pos] = u;
                    atomicAdd(&histA[u & 0x3FFu], 1u);
                }
            }
        }
        __syncthreads();

        SELECT3(1024, histA, histA, 0);
        c3 = s_chosen;
        unsigned S2 = s_cnt2;

        // ---- pass D: final strictly-greater among exact-tie bin ----
        if (S2 <= BUF2) {
            for (unsigned i = tid; i < S2; i += 1024) {
                unsigned u = buf2[i];
                if ((int)(u & 0x3FFu) > c3) acc += __uint_as_float(u);
            }
        } else {
            for (int i = tid; i < P; i += 1024) {
                unsigned u = sd[i];
                if ((int)(u >> 21) == c1 && (int)((u >> 10) & 0x7FFu) == c2 &&
                    (int)(u & 0x3FFu) > c3)
                    acc += __uint_as_float(u);
            }
        }

        #pragma unroll
        for (int off = 16; off; off >>= 1)
            acc += __shfl_xor_sync(0xffffffffu, acc, off);
        if (lane == 0) fred[wrp] = acc;
        __syncthreads();
        if (tid == 0) {
            float tot = 0.f;
            #pragma unroll
            for (int w = 0; w < 32; w++) tot += fred[w];
            unsigned tbits = ((unsigned)c1 << 21) | ((unsigned)c2 << 10) | (unsigned)c3;
            g_cneg[b] = tot + (float)s_krem * __uint_as_float(tbits);
        }
    } else {
        if (tid == 0) g_cneg[b] = 0.0f;
    }

    // ---------------- last-block final reduction ----------------
    if (tid == 0) {
        __threadfence();
        unsigned old = atomicAdd(&g_done, 1u);
        s_last = (old == (unsigned)(B - 1));
    }
    __syncthreads();
    if (!s_last) return;
    __threadfence();

    double a = 0.0, cc = 0.0;
    int n = 0;
    int tot = B * nb;
    for (int i = tid; i < tot; i += 1024) { a += (double)g_pl[i]; cc += (double)g_pc[i]; }
    for (int i = tid; i < B; i += 1024) {
        a  += (double)g_fl[i];
        cc += (double)g_fc[i] + (double)g_cneg[i];
        n  += g_npos[i];
    }
    #pragma unroll
    for (int off = 16; off; off >>= 1) {
        a  += __shfl_xor_sync(0xffffffffu, a, off);
        cc += __shfl_xor_sync(0xffffffffu, cc, off);
        n  += __shfl_xor_sync(0xffffffffu, n, off);
    }
    if (lane == 0) { dredA[wrp] = a; dredC[wrp] = cc; ired[wrp] = n; }
    __syncthreads();
    if (tid == 0) {
        double ta = 0.0, tc = 0.0; int tn = 0;
        #pragma unroll
        for (int w = 0; w < 32; w++) { ta += dredA[w]; tc += dredC[w]; tn += ired[w]; }
        double N = (double)tn;
        if (N < 1.0) N = 1.0;
        out[0] = (float)(ta / N);
        out[1] = (float)(tc / N);
        g_done = 0u;
    }
}

extern "C" void kernel_launch(void* const* d_in, const int* in_sizes, int n_in,
                              void* d_out, int out_size) {
    const float* loc     = (const float*)d_in[0];
    const float* conf    = (const float*)d_in[1];
    const float* priors  = (const float*)d_in[2];
    const float* targets = (const float*)d_in[3];
    float* out = (float*)d_out;

    int P = in_sizes[2] / 4;
    int B = in_sizes[0] / (P * 4);
    int O = in_sizes[3] / (B * 5);

    static int smem_set = 0;
    if (!smem_set) {
        cudaFuncSetAttribute(k_topk, cudaFuncAttributeMaxDynamicSharedMemorySize,
                             DSMEM_WORDS * 4);
        smem_set = 1;
    }

    int nb;
    if (O == 16 && (P % 1024) == 0) {
        nb = P / 1024;
        dim3 grid(nb, B);
        k_main4<<<grid, 256>>>(loc, conf, priors, targets, P);
    } else {
        nb = (P + 255) / 256;
        dim3 grid(nb, B);
        k_main1<<<grid, 256>>>(loc, conf, priors, targets, P, O);
    }
    k_topk<<<B, 1024, DSMEM_WORDS * 4>>>(
        loc, conf, priors, targets, out, P, O, nb, B);
}